// round 1
// baseline (speedup 1.0000x reference)
#include <cuda_runtime.h>
#include <math.h>

#define NE 8
#define H 1024
#define F 3584
#define T 4096

#define BM 64
#define BN 64
#define BK 16
#define MT (T / BM)   // 64 m-tiles per expert (worst case)

// ---------------- scratch (device globals: allocation-free) ----------------
__device__ int   g_count[NE];
__device__ int   g_idx[NE * T];
__device__ float g_wt[NE * T];
// per-assignment activations: capacity T rows per expert, F cols each (~470MB)
__device__ float g_act[(size_t)NE * T * F];

// ---------------- kernel 0: zero y + counters ----------------
__global__ void zero_kernel(float* __restrict__ y) {
    size_t n = (size_t)T * H;
    size_t stride = (size_t)gridDim.x * blockDim.x;
    for (size_t i = (size_t)blockIdx.x * blockDim.x + threadIdx.x; i < n; i += stride)
        y[i] = 0.0f;
    if (blockIdx.x == 0 && threadIdx.x < NE) g_count[threadIdx.x] = 0;
}

// ---------------- kernel 1: router (warp per token) ----------------
__global__ void router_kernel(const float* __restrict__ x,
                              const float* __restrict__ gw,
                              float* __restrict__ logits_out,
                              int write_logits) {
    int warp = threadIdx.x >> 5;
    int lane = threadIdx.x & 31;
    int t = blockIdx.x * 4 + warp;
    if (t >= T) return;
    const float* xr = x + (size_t)t * H;

    float acc[NE];
#pragma unroll
    for (int e = 0; e < NE; e++) acc[e] = 0.0f;

    for (int k = lane; k < H; k += 32) {
        float xv = xr[k];
        const float* g = gw + (size_t)k * NE;
#pragma unroll
        for (int e = 0; e < NE; e++) acc[e] += xv * g[e];
    }
#pragma unroll
    for (int off = 16; off > 0; off >>= 1)
#pragma unroll
        for (int e = 0; e < NE; e++)
            acc[e] += __shfl_down_sync(0xffffffffu, acc[e], off);

    if (lane == 0) {
        if (write_logits) {
#pragma unroll
            for (int e = 0; e < NE; e++) logits_out[(size_t)t * NE + e] = acc[e];
        }
        // top-1: strict > keeps lowest index on ties (matches jax top_k)
        int i1 = 0;
#pragma unroll
        for (int e = 1; e < NE; e++) if (acc[e] > acc[i1]) i1 = e;
        int i2 = (i1 == 0) ? 1 : 0;
#pragma unroll
        for (int e = 0; e < NE; e++)
            if (e != i1 && acc[e] > acc[i2]) i2 = e;

        // normalized top-2 weights: w1 = p1/(p1+p2) = 1/(1+exp(l2-l1))
        float w1 = 1.0f / (1.0f + expf(acc[i2] - acc[i1]));
        float w2 = 1.0f / (1.0f + expf(acc[i1] - acc[i2]));

        int p1 = atomicAdd(&g_count[i1], 1);
        g_idx[i1 * T + p1] = t;
        g_wt[i1 * T + p1] = w1;
        int p2 = atomicAdd(&g_count[i2], 1);
        g_idx[i2 * T + p2] = t;
        g_wt[i2 * T + p2] = w2;
    }
}

// ---------------- kernel 2: gathered up+gate GEMM, fused SiLU*gate ----------------
__global__ __launch_bounds__(128) void upgate_kernel(const float* __restrict__ x,
                                                     const float* __restrict__ wup,
                                                     const float* __restrict__ wgate) {
    int e = blockIdx.x / MT;
    int mt = blockIdx.x % MT;
    int cnt = g_count[e];
    int row0 = mt * BM;
    if (row0 >= cnt) return;
    int f0 = blockIdx.y * BN;

    __shared__ float As[BK][BM];
    __shared__ float Bu[BK][BN];
    __shared__ float Bg[BK][BN];
    __shared__ int   toks[BM];

    int tid = threadIdx.x;
    if (tid < BM) {
        int r = row0 + tid;
        toks[tid] = (r < cnt) ? g_idx[e * T + r] : -1;
    }
    __syncthreads();

    const float* Wu = wup   + (size_t)e * H * F;
    const float* Wg = wgate + (size_t)e * H * F;

    float accU[4][8];
    float accG[4][8];
#pragma unroll
    for (int i = 0; i < 4; i++)
#pragma unroll
        for (int j = 0; j < 8; j++) { accU[i][j] = 0.0f; accG[i][j] = 0.0f; }

    int tr = tid >> 3;  // 0..15
    int tc = tid & 7;   // 0..7

    for (int k0 = 0; k0 < H; k0 += BK) {
        // A tile: 64 rows x 16 k (gathered), 256 float4 loads
#pragma unroll
        for (int j = 0; j < 2; j++) {
            int li = tid + j * 128;
            int m  = li >> 2;
            int kq = (li & 3) * 4;
            float4 v = make_float4(0.f, 0.f, 0.f, 0.f);
            int tok = toks[m];
            if (tok >= 0) v = *(const float4*)(x + (size_t)tok * H + k0 + kq);
            As[kq + 0][m] = v.x; As[kq + 1][m] = v.y;
            As[kq + 2][m] = v.z; As[kq + 3][m] = v.w;
        }
        // B tiles: 16 k x 64 f each
#pragma unroll
        for (int j = 0; j < 2; j++) {
            int li = tid + j * 128;
            int kk = li >> 4;
            int fq = (li & 15) * 4;
            size_t gi = (size_t)(k0 + kk) * F + f0 + fq;
            *(float4*)&Bu[kk][fq] = *(const float4*)(Wu + gi);
            *(float4*)&Bg[kk][fq] = *(const float4*)(Wg + gi);
        }
        __syncthreads();
#pragma unroll
        for (int k = 0; k < BK; k++) {
            float a[4], bu[8], bg[8];
#pragma unroll
            for (int i = 0; i < 4; i++) a[i] = As[k][tr * 4 + i];
#pragma unroll
            for (int j = 0; j < 8; j++) { bu[j] = Bu[k][tc * 8 + j]; bg[j] = Bg[k][tc * 8 + j]; }
#pragma unroll
            for (int i = 0; i < 4; i++)
#pragma unroll
                for (int j = 0; j < 8; j++) {
                    accU[i][j] += a[i] * bu[j];
                    accG[i][j] += a[i] * bg[j];
                }
        }
        __syncthreads();
    }

    // epilogue: act = silu(up) * gate -> scratch
#pragma unroll
    for (int i = 0; i < 4; i++) {
        int r = row0 + tr * 4 + i;
        if (r >= cnt) continue;
        float* arow = g_act + ((size_t)e * T + r) * F + f0 + tc * 8;
#pragma unroll
        for (int j = 0; j < 8; j++) {
            float u = accU[i][j];
            float s = u / (1.0f + expf(-u));
            arow[j] = s * accG[i][j];
        }
    }
}

// ---------------- kernel 3: down GEMM + weighted scatter ----------------
__global__ __launch_bounds__(128) void down_kernel(const float* __restrict__ wdown,
                                                   float* __restrict__ y) {
    int e = blockIdx.x / MT;
    int mt = blockIdx.x % MT;
    int cnt = g_count[e];
    int row0 = mt * BM;
    if (row0 >= cnt) return;
    int n0 = blockIdx.y * BN;

    __shared__ float As[BK][BM];
    __shared__ float Bs[BK][BN];

    const float* A = g_act + ((size_t)e * T + row0) * F;   // [rows][F], contiguous
    const float* W = wdown + (size_t)e * F * H;

    float acc[4][8];
#pragma unroll
    for (int i = 0; i < 4; i++)
#pragma unroll
        for (int j = 0; j < 8; j++) acc[i][j] = 0.0f;

    int tid = threadIdx.x;
    int tr = tid >> 3;
    int tc = tid & 7;

    for (int k0 = 0; k0 < F; k0 += BK) {
#pragma unroll
        for (int j = 0; j < 2; j++) {
            int li = tid + j * 128;
            int m  = li >> 2;
            int kq = (li & 3) * 4;
            float4 v = make_float4(0.f, 0.f, 0.f, 0.f);
            if (row0 + m < cnt) v = *(const float4*)(A + (size_t)m * F + k0 + kq);
            As[kq + 0][m] = v.x; As[kq + 1][m] = v.y;
            As[kq + 2][m] = v.z; As[kq + 3][m] = v.w;
        }
#pragma unroll
        for (int j = 0; j < 2; j++) {
            int li = tid + j * 128;
            int kk = li >> 4;
            int nq = (li & 15) * 4;
            *(float4*)&Bs[kk][nq] = *(const float4*)(W + (size_t)(k0 + kk) * H + n0 + nq);
        }
        __syncthreads();
#pragma unroll
        for (int k = 0; k < BK; k++) {
            float a[4], b[8];
#pragma unroll
            for (int i = 0; i < 4; i++) a[i] = As[k][tr * 4 + i];
#pragma unroll
            for (int j = 0; j < 8; j++) b[j] = Bs[k][tc * 8 + j];
#pragma unroll
            for (int i = 0; i < 4; i++)
#pragma unroll
                for (int j = 0; j < 8; j++) acc[i][j] += a[i] * b[j];
        }
        __syncthreads();
    }

#pragma unroll
    for (int i = 0; i < 4; i++) {
        int r = row0 + tr * 4 + i;
        if (r >= cnt) continue;
        int tok = g_idx[e * T + r];
        float wgt = g_wt[e * T + r];
        float* yr = y + (size_t)tok * H + n0 + tc * 8;
#pragma unroll
        for (int j = 0; j < 8; j++)
            atomicAdd(&yr[j], acc[i][j] * wgt);   // exactly 2 adds/element: commutative
    }
}

// ---------------- launch ----------------
extern "C" void kernel_launch(void* const* d_in, const int* in_sizes, int n_in,
                              void* d_out, int out_size) {
    const float* x     = (const float*)d_in[0];   // [B*S, H]
    const float* gw    = (const float*)d_in[1];   // [H, NE]
    const float* wup   = (const float*)d_in[2];   // [NE, H, F]
    const float* wgate = (const float*)d_in[3];   // [NE, H, F]
    const float* wdown = (const float*)d_in[4];   // [NE, F, H]
    float* y = (float*)d_out;

    int write_logits = (out_size >= T * H + T * NE) ? 1 : 0;
    float* logits = y + (size_t)T * H;

    zero_kernel<<<256, 256>>>(y);
    router_kernel<<<T / 4, 128>>>(x, gw, logits, write_logits);
    upgate_kernel<<<dim3(NE * MT, F / BN), 128>>>(x, wup, wgate);
    down_kernel<<<dim3(NE * MT, H / BN), 128>>>(wdown, y);
}

// round 3
// speedup vs baseline: 3.6098x; 3.6098x over previous
#include <cuda_runtime.h>
#include <math.h>
#include <stdint.h>

#define NE 8
#define H 1024
#define F 3584
#define T 4096

#define BM 64
#define BN 64
#define BK 32
#define MT (T / BM)

// ---------------- scratch ----------------
__device__ int   g_count[NE];
__device__ int   g_idx[NE * T];
__device__ float g_wt[NE * T];
__device__ float g_act[(size_t)NE * T * F];

// ---------------- helpers ----------------
__device__ __forceinline__ uint32_t f2tf(float f) {
    uint32_t u;
    asm("cvt.rna.tf32.f32 %0, %1;" : "=r"(u) : "f"(f));
    return u;
}

__device__ __forceinline__ void mma8(float* d, const uint32_t* a, const uint32_t* b) {
    asm volatile(
        "mma.sync.aligned.m16n8k8.row.col.f32.tf32.tf32.f32 "
        "{%0,%1,%2,%3},{%4,%5,%6,%7},{%8,%9},{%0,%1,%2,%3};"
        : "+f"(d[0]), "+f"(d[1]), "+f"(d[2]), "+f"(d[3])
        : "r"(a[0]), "r"(a[1]), "r"(a[2]), "r"(a[3]), "r"(b[0]), "r"(b[1]));
}

// ---------------- kernel 0: zero y + counters ----------------
__global__ void zero_kernel(float* __restrict__ y) {
    size_t n = (size_t)T * H;
    size_t stride = (size_t)gridDim.x * blockDim.x;
    for (size_t i = (size_t)blockIdx.x * blockDim.x + threadIdx.x; i < n; i += stride)
        y[i] = 0.0f;
    if (blockIdx.x == 0 && threadIdx.x < NE) g_count[threadIdx.x] = 0;
}

// ---------------- kernel 1: router ----------------
__global__ void router_kernel(const float* __restrict__ x,
                              const float* __restrict__ gw,
                              float* __restrict__ logits_out,
                              int write_logits) {
    int warp = threadIdx.x >> 5;
    int lane = threadIdx.x & 31;
    int t = blockIdx.x * 4 + warp;
    if (t >= T) return;
    const float* xr = x + (size_t)t * H;

    float acc[NE];
#pragma unroll
    for (int e = 0; e < NE; e++) acc[e] = 0.0f;

    for (int k = lane; k < H; k += 32) {
        float xv = xr[k];
        const float* g = gw + (size_t)k * NE;
#pragma unroll
        for (int e = 0; e < NE; e++) acc[e] += xv * g[e];
    }
#pragma unroll
    for (int off = 16; off > 0; off >>= 1)
#pragma unroll
        for (int e = 0; e < NE; e++)
            acc[e] += __shfl_down_sync(0xffffffffu, acc[e], off);

    if (lane == 0) {
        if (write_logits) {
#pragma unroll
            for (int e = 0; e < NE; e++) logits_out[(size_t)t * NE + e] = acc[e];
        }
        int i1 = 0;
#pragma unroll
        for (int e = 1; e < NE; e++) if (acc[e] > acc[i1]) i1 = e;
        int i2 = (i1 == 0) ? 1 : 0;
#pragma unroll
        for (int e = 0; e < NE; e++)
            if (e != i1 && acc[e] > acc[i2]) i2 = e;

        float w1 = 1.0f / (1.0f + expf(acc[i2] - acc[i1]));
        float w2 = 1.0f / (1.0f + expf(acc[i1] - acc[i2]));

        int p1 = atomicAdd(&g_count[i1], 1);
        g_idx[i1 * T + p1] = t;
        g_wt[i1 * T + p1] = w1;
        int p2 = atomicAdd(&g_count[i2], 1);
        g_idx[i2 * T + p2] = t;
        g_wt[i2 * T + p2] = w2;
    }
}

// ---------------- kernel 2: tf32 tensor-core up+gate GEMM + SiLU ----------------
// block: 128 threads (4 warps, 2x2 warp grid), tile 64x64, BK=32
__global__ __launch_bounds__(128) void upgate_kernel(const float* __restrict__ x,
                                                     const float* __restrict__ wup,
                                                     const float* __restrict__ wgate) {
    int e = blockIdx.x / MT;
    int mtile = blockIdx.x % MT;
    int cnt = g_count[e];
    int row0 = mtile * BM;
    if (row0 >= cnt) return;
    int f0 = blockIdx.y * BN;

    __shared__ uint32_t As[BM][36];      // stride 36 -> conflict-free frag loads
    __shared__ uint32_t BuS[BK][72];     // stride 72 -> conflict-free frag loads
    __shared__ uint32_t BgS[BK][72];
    __shared__ int toks[BM];

    int tid = threadIdx.x;
    if (tid < BM) {
        int r = row0 + tid;
        toks[tid] = (r < cnt) ? g_idx[e * T + r] : -1;
    }
    __syncthreads();

    const float* Wu = wup   + (size_t)e * H * F;
    const float* Wg = wgate + (size_t)e * H * F;

    int wid = tid >> 5, lane = tid & 31;
    int wr = (wid >> 1) * 32;    // warp row offset in tile
    int wn = (wid & 1) * 32;     // warp col offset in tile
    int qr = lane >> 2, qc = lane & 3;

    float accU[2][4][4];
    float accG[2][4][4];
#pragma unroll
    for (int mt = 0; mt < 2; mt++)
#pragma unroll
        for (int nt = 0; nt < 4; nt++)
#pragma unroll
            for (int i = 0; i < 4; i++) { accU[mt][nt][i] = 0.0f; accG[mt][nt][i] = 0.0f; }

    for (int k0 = 0; k0 < H; k0 += BK) {
        // A: 64 rows x 32 k (gathered)
#pragma unroll
        for (int j = 0; j < 4; j++) {
            int li = tid + j * 128;
            int m  = li >> 3;
            int cq = (li & 7) * 4;
            float4 v = make_float4(0.f, 0.f, 0.f, 0.f);
            int tok = toks[m];
            if (tok >= 0) v = *(const float4*)(x + (size_t)tok * H + k0 + cq);
            As[m][cq + 0] = f2tf(v.x); As[m][cq + 1] = f2tf(v.y);
            As[m][cq + 2] = f2tf(v.z); As[m][cq + 3] = f2tf(v.w);
        }
        // B tiles: 32 k x 64 n
#pragma unroll
        for (int j = 0; j < 4; j++) {
            int li = tid + j * 128;
            int kk = li >> 4;
            int nq = (li & 15) * 4;
            size_t gi = (size_t)(k0 + kk) * F + f0 + nq;
            float4 u = *(const float4*)(Wu + gi);
            float4 g = *(const float4*)(Wg + gi);
            BuS[kk][nq + 0] = f2tf(u.x); BuS[kk][nq + 1] = f2tf(u.y);
            BuS[kk][nq + 2] = f2tf(u.z); BuS[kk][nq + 3] = f2tf(u.w);
            BgS[kk][nq + 0] = f2tf(g.x); BgS[kk][nq + 1] = f2tf(g.y);
            BgS[kk][nq + 2] = f2tf(g.z); BgS[kk][nq + 3] = f2tf(g.w);
        }
        __syncthreads();

#pragma unroll
        for (int ks = 0; ks < BK / 8; ks++) {
            uint32_t a[2][4], bu[4][2], bg[4][2];
#pragma unroll
            for (int mt = 0; mt < 2; mt++) {
                int r = wr + mt * 16 + qr;
                int c = ks * 8 + qc;
                a[mt][0] = As[r][c];     a[mt][1] = As[r + 8][c];
                a[mt][2] = As[r][c + 4]; a[mt][3] = As[r + 8][c + 4];
            }
#pragma unroll
            for (int nt = 0; nt < 4; nt++) {
                int n = wn + nt * 8 + qr;
                int c = ks * 8 + qc;
                bu[nt][0] = BuS[c][n]; bu[nt][1] = BuS[c + 4][n];
                bg[nt][0] = BgS[c][n]; bg[nt][1] = BgS[c + 4][n];
            }
#pragma unroll
            for (int mt = 0; mt < 2; mt++)
#pragma unroll
                for (int nt = 0; nt < 4; nt++) {
                    mma8(accU[mt][nt], a[mt], bu[nt]);
                    mma8(accG[mt][nt], a[mt], bg[nt]);
                }
        }
        __syncthreads();
    }

    // epilogue: silu(up)*gate -> scratch
#pragma unroll
    for (int mt = 0; mt < 2; mt++)
#pragma unroll
        for (int nt = 0; nt < 4; nt++) {
            int col = f0 + wn + nt * 8 + 2 * qc;
#pragma unroll
            for (int h = 0; h < 2; h++) {
                int r = row0 + wr + mt * 16 + qr + h * 8;
                if (r >= cnt) continue;
                float u0 = accU[mt][nt][h * 2 + 0], u1 = accU[mt][nt][h * 2 + 1];
                float g0 = accG[mt][nt][h * 2 + 0], g1 = accG[mt][nt][h * 2 + 1];
                float s0 = u0 / (1.0f + expf(-u0)) * g0;
                float s1 = u1 / (1.0f + expf(-u1)) * g1;
                *(float2*)(g_act + ((size_t)e * T + r) * F + col) = make_float2(s0, s1);
            }
        }
}

// ---------------- kernel 3: tf32 tensor-core down GEMM + weighted scatter ----------------
__global__ __launch_bounds__(128) void down_kernel(const float* __restrict__ wdown,
                                                   float* __restrict__ y) {
    int e = blockIdx.x / MT;
    int mtile = blockIdx.x % MT;
    int cnt = g_count[e];
    int row0 = mtile * BM;
    if (row0 >= cnt) return;
    int n0 = blockIdx.y * BN;

    __shared__ uint32_t As[BM][36];
    __shared__ uint32_t Bs[BK][72];

    const float* A = g_act + ((size_t)e * T + row0) * F;
    const float* W = wdown + (size_t)e * F * H;

    int tid = threadIdx.x;
    int wid = tid >> 5, lane = tid & 31;
    int wr = (wid >> 1) * 32;
    int wn = (wid & 1) * 32;
    int qr = lane >> 2, qc = lane & 3;

    float acc[2][4][4];
#pragma unroll
    for (int mt = 0; mt < 2; mt++)
#pragma unroll
        for (int nt = 0; nt < 4; nt++)
#pragma unroll
            for (int i = 0; i < 4; i++) acc[mt][nt][i] = 0.0f;

    for (int k0 = 0; k0 < F; k0 += BK) {
#pragma unroll
        for (int j = 0; j < 4; j++) {
            int li = tid + j * 128;
            int m  = li >> 3;
            int cq = (li & 7) * 4;
            float4 v = make_float4(0.f, 0.f, 0.f, 0.f);
            if (row0 + m < cnt) v = *(const float4*)(A + (size_t)m * F + k0 + cq);
            As[m][cq + 0] = f2tf(v.x); As[m][cq + 1] = f2tf(v.y);
            As[m][cq + 2] = f2tf(v.z); As[m][cq + 3] = f2tf(v.w);
        }
#pragma unroll
        for (int j = 0; j < 4; j++) {
            int li = tid + j * 128;
            int kk = li >> 4;
            int nq = (li & 15) * 4;
            float4 b = *(const float4*)(W + (size_t)(k0 + kk) * H + n0 + nq);
            Bs[kk][nq + 0] = f2tf(b.x); Bs[kk][nq + 1] = f2tf(b.y);
            Bs[kk][nq + 2] = f2tf(b.z); Bs[kk][nq + 3] = f2tf(b.w);
        }
        __syncthreads();

#pragma unroll
        for (int ks = 0; ks < BK / 8; ks++) {
            uint32_t a[2][4], b[4][2];
#pragma unroll
            for (int mt = 0; mt < 2; mt++) {
                int r = wr + mt * 16 + qr;
                int c = ks * 8 + qc;
                a[mt][0] = As[r][c];     a[mt][1] = As[r + 8][c];
                a[mt][2] = As[r][c + 4]; a[mt][3] = As[r + 8][c + 4];
            }
#pragma unroll
            for (int nt = 0; nt < 4; nt++) {
                int n = wn + nt * 8 + qr;
                int c = ks * 8 + qc;
                b[nt][0] = Bs[c][n]; b[nt][1] = Bs[c + 4][n];
            }
#pragma unroll
            for (int mt = 0; mt < 2; mt++)
#pragma unroll
                for (int nt = 0; nt < 4; nt++)
                    mma8(acc[mt][nt], a[mt], b[nt]);
        }
        __syncthreads();
    }

#pragma unroll
    for (int mt = 0; mt < 2; mt++)
#pragma unroll
        for (int nt = 0; nt < 4; nt++) {
            int col = n0 + wn + nt * 8 + 2 * qc;
#pragma unroll
            for (int h = 0; h < 2; h++) {
                int r = row0 + wr + mt * 16 + qr + h * 8;
                if (r >= cnt) continue;
                int tok = g_idx[e * T + r];
                float wgt = g_wt[e * T + r];
                float* yr = y + (size_t)tok * H + col;
                atomicAdd(&yr[0], acc[mt][nt][h * 2 + 0] * wgt);
                atomicAdd(&yr[1], acc[mt][nt][h * 2 + 1] * wgt);
            }
        }
}

// ---------------- launch ----------------
extern "C" void kernel_launch(void* const* d_in, const int* in_sizes, int n_in,
                              void* d_out, int out_size) {
    const float* x     = (const float*)d_in[0];
    const float* gw    = (const float*)d_in[1];
    const float* wup   = (const float*)d_in[2];
    const float* wgate = (const float*)d_in[3];
    const float* wdown = (const float*)d_in[4];
    float* y = (float*)d_out;

    int write_logits = (out_size >= T * H + T * NE) ? 1 : 0;
    float* logits = y + (size_t)T * H;

    zero_kernel<<<256, 256>>>(y);
    router_kernel<<<T / 4, 128>>>(x, gw, logits, write_logits);
    upgate_kernel<<<dim3(NE * MT, F / BN), 128>>>(x, wup, wgate);
    down_kernel<<<dim3(NE * MT, H / BN), 128>>>(wdown, y);
}

// round 5
// speedup vs baseline: 3.9415x; 1.0919x over previous
#include <cuda_runtime.h>
#include <math.h>
#include <stdint.h>

#define NE 8
#define H 1024
#define F 3584
#define T 4096

#define BM 128
#define BK 32
#define MT (T / BM)          // 32 m-tiles per expert

#define AS_STRIDE 36
#define AS_WORDS (BM * AS_STRIDE)   // 4608
#define BU_STRIDE 72
#define BU_WORDS (BK * BU_STRIDE)   // 2304
#define BD_STRIDE 136
#define BD_WORDS (BK * BD_STRIDE)   // 4352

#define SMEM_UPGATE ((2 * AS_WORDS + 4 * BU_WORDS) * 4)   // 73728 B
#define SMEM_DOWN   ((2 * AS_WORDS + 2 * BD_WORDS) * 4)   // 71680 B

// ---------------- scratch ----------------
__device__ int   g_count[NE];
__device__ int   g_idx[NE * T];
__device__ float g_wt[NE * T];
__device__ float g_act[(size_t)NE * T * F];

// ---------------- helpers ----------------
__device__ __forceinline__ uint32_t f2tf(float f) {
    uint32_t u;
    asm("cvt.rna.tf32.f32 %0, %1;" : "=r"(u) : "f"(f));
    return u;
}
__device__ __forceinline__ uint4 f2tf4(float4 v) {
    uint4 t;
    t.x = f2tf(v.x); t.y = f2tf(v.y); t.z = f2tf(v.z); t.w = f2tf(v.w);
    return t;
}
__device__ __forceinline__ void mma8(float* d, const uint32_t* a, const uint32_t* b) {
    asm volatile(
        "mma.sync.aligned.m16n8k8.row.col.f32.tf32.tf32.f32 "
        "{%0,%1,%2,%3},{%4,%5,%6,%7},{%8,%9},{%0,%1,%2,%3};"
        : "+f"(d[0]), "+f"(d[1]), "+f"(d[2]), "+f"(d[3])
        : "r"(a[0]), "r"(a[1]), "r"(a[2]), "r"(a[3]), "r"(b[0]), "r"(b[1]));
}

// ---------------- kernel 0: zero y + counters ----------------
__global__ void zero_kernel(float* __restrict__ y) {
    size_t n = (size_t)T * H;
    size_t stride = (size_t)gridDim.x * blockDim.x;
    for (size_t i = (size_t)blockIdx.x * blockDim.x + threadIdx.x; i < n; i += stride)
        y[i] = 0.0f;
    if (blockIdx.x == 0 && threadIdx.x < NE) g_count[threadIdx.x] = 0;
}

// ---------------- kernel 1: router ----------------
__global__ void router_kernel(const float* __restrict__ x,
                              const float* __restrict__ gw,
                              float* __restrict__ logits_out,
                              int write_logits) {
    int warp = threadIdx.x >> 5;
    int lane = threadIdx.x & 31;
    int t = blockIdx.x * 4 + warp;
    if (t >= T) return;
    const float* xr = x + (size_t)t * H;

    float acc[NE];
#pragma unroll
    for (int e = 0; e < NE; e++) acc[e] = 0.0f;

    for (int k = lane; k < H; k += 32) {
        float xv = xr[k];
        const float* g = gw + (size_t)k * NE;
#pragma unroll
        for (int e = 0; e < NE; e++) acc[e] += xv * g[e];
    }
#pragma unroll
    for (int off = 16; off > 0; off >>= 1)
#pragma unroll
        for (int e = 0; e < NE; e++)
            acc[e] += __shfl_down_sync(0xffffffffu, acc[e], off);

    if (lane == 0) {
        if (write_logits) {
#pragma unroll
            for (int e = 0; e < NE; e++) logits_out[(size_t)t * NE + e] = acc[e];
        }
        int i1 = 0;
#pragma unroll
        for (int e = 1; e < NE; e++) if (acc[e] > acc[i1]) i1 = e;
        int i2 = (i1 == 0) ? 1 : 0;
#pragma unroll
        for (int e = 0; e < NE; e++)
            if (e != i1 && acc[e] > acc[i2]) i2 = e;

        float w1 = 1.0f / (1.0f + expf(acc[i2] - acc[i1]));
        float w2 = 1.0f / (1.0f + expf(acc[i1] - acc[i2]));

        int p1 = atomicAdd(&g_count[i1], 1);
        g_idx[i1 * T + p1] = t;
        g_wt[i1 * T + p1] = w1;
        int p2 = atomicAdd(&g_count[i2], 1);
        g_idx[i2 * T + p2] = t;
        g_wt[i2 * T + p2] = w2;
    }
}

// ---------------- kernel 2: pipelined tf32 up+gate GEMM + SiLU ----------------
// 256 threads, 8 warps (4 row x 2 col), block tile 128x64 (x2 matrices),
// warp tile 32x32, double-buffered smem, register prefetch.
__global__ __launch_bounds__(256) void upgate_kernel(const float* __restrict__ x,
                                                     const float* __restrict__ wup,
                                                     const float* __restrict__ wgate) {
    extern __shared__ uint32_t sm[];
    uint32_t* AsB = sm;                          // [2][BM][36]
    uint32_t* BuB = sm + 2 * AS_WORDS;           // [2][BK][72]
    uint32_t* BgB = BuB + 2 * BU_WORDS;          // [2][BK][72]
    __shared__ int toks[BM];

    int e = blockIdx.x / MT;
    int mtile = blockIdx.x % MT;
    int cnt = g_count[e];
    int row0 = mtile * BM;
    if (row0 >= cnt) return;
    int f0 = blockIdx.y * 64;

    int tid = threadIdx.x;
    if (tid < BM) {
        int r = row0 + tid;
        toks[tid] = (r < cnt) ? g_idx[e * T + r] : -1;
    }
    __syncthreads();

    const float* Wu = wup   + (size_t)e * H * F;
    const float* Wg = wgate + (size_t)e * H * F;

    // per-thread load geometry
    int am[4], ac[4];
    const float* aptr[4];
    bool aval[4];
#pragma unroll
    for (int j = 0; j < 4; j++) {
        int li = tid + j * 256;
        am[j] = li >> 3;
        ac[j] = (li & 7) * 4;
        int tok = toks[am[j]];
        aval[j] = (tok >= 0);
        aptr[j] = x + (size_t)(aval[j] ? tok : 0) * H + ac[j];
    }
    int bk_[2], bn_[2];
#pragma unroll
    for (int j = 0; j < 2; j++) {
        int li = tid + j * 256;
        bk_[j] = li >> 4;
        bn_[j] = (li & 15) * 4;
    }

    float4 ra[4], ru[2], rg[2];
    // prefetch k0 = 0
#pragma unroll
    for (int j = 0; j < 4; j++)
        ra[j] = aval[j] ? *(const float4*)(aptr[j]) : make_float4(0.f, 0.f, 0.f, 0.f);
#pragma unroll
    for (int j = 0; j < 2; j++) {
        size_t gi = (size_t)bk_[j] * F + f0 + bn_[j];
        ru[j] = *(const float4*)(Wu + gi);
        rg[j] = *(const float4*)(Wg + gi);
    }
    // store into buffer 0
#pragma unroll
    for (int j = 0; j < 4; j++)
        *(uint4*)(AsB + am[j] * AS_STRIDE + ac[j]) = f2tf4(ra[j]);
#pragma unroll
    for (int j = 0; j < 2; j++) {
        *(uint4*)(BuB + bk_[j] * BU_STRIDE + bn_[j]) = f2tf4(ru[j]);
        *(uint4*)(BgB + bk_[j] * BU_STRIDE + bn_[j]) = f2tf4(rg[j]);
    }
    __syncthreads();

    int wid = tid >> 5, lane = tid & 31;
    int wr = (wid >> 1) * 32;
    int wn = (wid & 1) * 32;
    int qr = lane >> 2, qc = lane & 3;

    float accU[2][4][4], accG[2][4][4];
#pragma unroll
    for (int mt = 0; mt < 2; mt++)
#pragma unroll
        for (int nt = 0; nt < 4; nt++)
#pragma unroll
            for (int i = 0; i < 4; i++) { accU[mt][nt][i] = 0.0f; accG[mt][nt][i] = 0.0f; }

    int buf = 0;
    for (int k0 = 0; k0 < H; k0 += BK) {
        bool has_next = (k0 + BK < H);
        if (has_next) {
            int kn = k0 + BK;
#pragma unroll
            for (int j = 0; j < 4; j++)
                ra[j] = aval[j] ? *(const float4*)(aptr[j] + kn) : make_float4(0.f, 0.f, 0.f, 0.f);
#pragma unroll
            for (int j = 0; j < 2; j++) {
                size_t gi = (size_t)(kn + bk_[j]) * F + f0 + bn_[j];
                ru[j] = *(const float4*)(Wu + gi);
                rg[j] = *(const float4*)(Wg + gi);
            }
        }

        const uint32_t* Ab = AsB + buf * AS_WORDS;
        const uint32_t* Ub = BuB + buf * BU_WORDS;
        const uint32_t* Gb = BgB + buf * BU_WORDS;
#pragma unroll
        for (int ks = 0; ks < 4; ks++) {
            int c = ks * 8 + qc;
            uint32_t a[2][4], bu[4][2], bg[4][2];
#pragma unroll
            for (int mt = 0; mt < 2; mt++) {
                const uint32_t* ap = Ab + (wr + mt * 16 + qr) * AS_STRIDE + c;
                a[mt][0] = ap[0];
                a[mt][1] = ap[8 * AS_STRIDE];
                a[mt][2] = ap[4];
                a[mt][3] = ap[8 * AS_STRIDE + 4];
            }
#pragma unroll
            for (int nt = 0; nt < 4; nt++) {
                int n = wn + nt * 8 + qr;
                bu[nt][0] = Ub[c * BU_STRIDE + n];
                bu[nt][1] = Ub[(c + 4) * BU_STRIDE + n];
                bg[nt][0] = Gb[c * BU_STRIDE + n];
                bg[nt][1] = Gb[(c + 4) * BU_STRIDE + n];
            }
#pragma unroll
            for (int mt = 0; mt < 2; mt++)
#pragma unroll
                for (int nt = 0; nt < 4; nt++) {
                    mma8(accU[mt][nt], a[mt], bu[nt]);
                    mma8(accG[mt][nt], a[mt], bg[nt]);
                }
        }

        if (has_next) {
            uint32_t* Ad = AsB + (buf ^ 1) * AS_WORDS;
            uint32_t* Ud = BuB + (buf ^ 1) * BU_WORDS;
            uint32_t* Gd = BgB + (buf ^ 1) * BU_WORDS;
#pragma unroll
            for (int j = 0; j < 4; j++)
                *(uint4*)(Ad + am[j] * AS_STRIDE + ac[j]) = f2tf4(ra[j]);
#pragma unroll
            for (int j = 0; j < 2; j++) {
                *(uint4*)(Ud + bk_[j] * BU_STRIDE + bn_[j]) = f2tf4(ru[j]);
                *(uint4*)(Gd + bk_[j] * BU_STRIDE + bn_[j]) = f2tf4(rg[j]);
            }
        }
        __syncthreads();
        buf ^= 1;
    }

    // epilogue: silu(up)*gate -> scratch
#pragma unroll
    for (int mt = 0; mt < 2; mt++)
#pragma unroll
        for (int nt = 0; nt < 4; nt++) {
            int col = f0 + wn + nt * 8 + 2 * qc;
#pragma unroll
            for (int h = 0; h < 2; h++) {
                int r = row0 + wr + mt * 16 + qr + h * 8;
                if (r >= cnt) continue;
                float u0 = accU[mt][nt][h * 2 + 0], u1 = accU[mt][nt][h * 2 + 1];
                float g0 = accG[mt][nt][h * 2 + 0], g1 = accG[mt][nt][h * 2 + 1];
                float s0 = u0 / (1.0f + expf(-u0)) * g0;
                float s1 = u1 / (1.0f + expf(-u1)) * g1;
                *(float2*)(g_act + ((size_t)e * T + r) * F + col) = make_float2(s0, s1);
            }
        }
}

// ---------------- kernel 3: pipelined tf32 down GEMM + weighted scatter ----------------
// 256 threads, 8 warps (4 row x 2 col), block tile 128x128, warp tile 32x64.
__global__ __launch_bounds__(256) void down_kernel(const float* __restrict__ wdown,
                                                   float* __restrict__ y) {
    extern __shared__ uint32_t sm[];
    uint32_t* AsB = sm;                 // [2][BM][36]
    uint32_t* BsB = sm + 2 * AS_WORDS;  // [2][BK][136]

    int e = blockIdx.x / MT;
    int mtile = blockIdx.x % MT;
    int cnt = g_count[e];
    int row0 = mtile * BM;
    if (row0 >= cnt) return;
    int n0 = blockIdx.y * 128;

    const float* A = g_act + ((size_t)e * T + row0) * F;
    const float* W = wdown + (size_t)e * F * H;

    int tid = threadIdx.x;

    int am[4], ac[4];
    const float* aptr[4];
    bool aval[4];
#pragma unroll
    for (int j = 0; j < 4; j++) {
        int li = tid + j * 256;
        am[j] = li >> 3;
        ac[j] = (li & 7) * 4;
        aval[j] = (row0 + am[j] < cnt);
        aptr[j] = A + (size_t)(aval[j] ? am[j] : 0) * F + ac[j];
    }
    int bk_[4], bn_[4];
#pragma unroll
    for (int j = 0; j < 4; j++) {
        int li = tid + j * 256;
        bk_[j] = li >> 5;
        bn_[j] = (li & 31) * 4;
    }

    float4 ra[4], rb[4];
#pragma unroll
    for (int j = 0; j < 4; j++)
        ra[j] = aval[j] ? *(const float4*)(aptr[j]) : make_float4(0.f, 0.f, 0.f, 0.f);
#pragma unroll
    for (int j = 0; j < 4; j++)
        rb[j] = *(const float4*)(W + (size_t)bk_[j] * H + n0 + bn_[j]);

#pragma unroll
    for (int j = 0; j < 4; j++)
        *(uint4*)(AsB + am[j] * AS_STRIDE + ac[j]) = f2tf4(ra[j]);
#pragma unroll
    for (int j = 0; j < 4; j++)
        *(uint4*)(BsB + bk_[j] * BD_STRIDE + bn_[j]) = f2tf4(rb[j]);
    __syncthreads();

    int wid = tid >> 5, lane = tid & 31;
    int wr = (wid >> 1) * 32;
    int wn = (wid & 1) * 64;
    int qr = lane >> 2, qc = lane & 3;

    float acc[2][8][4];
#pragma unroll
    for (int mt = 0; mt < 2; mt++)
#pragma unroll
        for (int nt = 0; nt < 8; nt++)
#pragma unroll
            for (int i = 0; i < 4; i++) acc[mt][nt][i] = 0.0f;

    int buf = 0;
    for (int k0 = 0; k0 < F; k0 += BK) {
        bool has_next = (k0 + BK < F);
        if (has_next) {
            int kn = k0 + BK;
#pragma unroll
            for (int j = 0; j < 4; j++)
                ra[j] = aval[j] ? *(const float4*)(aptr[j] + kn) : make_float4(0.f, 0.f, 0.f, 0.f);
#pragma unroll
            for (int j = 0; j < 4; j++)
                rb[j] = *(const float4*)(W + (size_t)(kn + bk_[j]) * H + n0 + bn_[j]);
        }

        const uint32_t* Ab = AsB + buf * AS_WORDS;
        const uint32_t* Bb = BsB + buf * BD_WORDS;
#pragma unroll
        for (int ks = 0; ks < 4; ks++) {
            int c = ks * 8 + qc;
            uint32_t a[2][4], b[8][2];
#pragma unroll
            for (int mt = 0; mt < 2; mt++) {
                const uint32_t* ap = Ab + (wr + mt * 16 + qr) * AS_STRIDE + c;
                a[mt][0] = ap[0];
                a[mt][1] = ap[8 * AS_STRIDE];
                a[mt][2] = ap[4];
                a[mt][3] = ap[8 * AS_STRIDE + 4];
            }
#pragma unroll
            for (int nt = 0; nt < 8; nt++) {
                int n = wn + nt * 8 + qr;
                b[nt][0] = Bb[c * BD_STRIDE + n];
                b[nt][1] = Bb[(c + 4) * BD_STRIDE + n];
            }
#pragma unroll
            for (int mt = 0; mt < 2; mt++)
#pragma unroll
                for (int nt = 0; nt < 8; nt++)
                    mma8(acc[mt][nt], a[mt], b[nt]);
        }

        if (has_next) {
            uint32_t* Ad = AsB + (buf ^ 1) * AS_WORDS;
            uint32_t* Bd = BsB + (buf ^ 1) * BD_WORDS;
#pragma unroll
            for (int j = 0; j < 4; j++)
                *(uint4*)(Ad + am[j] * AS_STRIDE + ac[j]) = f2tf4(ra[j]);
#pragma unroll
            for (int j = 0; j < 4; j++)
                *(uint4*)(Bd + bk_[j] * BD_STRIDE + bn_[j]) = f2tf4(rb[j]);
        }
        __syncthreads();
        buf ^= 1;
    }

    // weighted scatter
#pragma unroll
    for (int mt = 0; mt < 2; mt++)
#pragma unroll
        for (int nt = 0; nt < 8; nt++) {
            int col = n0 + wn + nt * 8 + 2 * qc;
#pragma unroll
            for (int h = 0; h < 2; h++) {
                int r = row0 + wr + mt * 16 + qr + h * 8;
                if (r >= cnt) continue;
                int tok = g_idx[e * T + r];
                float wgt = g_wt[e * T + r];
                float* yr = y + (size_t)tok * H + col;
                atomicAdd(&yr[0], acc[mt][nt][h * 2 + 0] * wgt);
                atomicAdd(&yr[1], acc[mt][nt][h * 2 + 1] * wgt);
            }
        }
}

// ---------------- launch ----------------
extern "C" void kernel_launch(void* const* d_in, const int* in_sizes, int n_in,
                              void* d_out, int out_size) {
    const float* x     = (const float*)d_in[0];
    const float* gw    = (const float*)d_in[1];
    const float* wup   = (const float*)d_in[2];
    const float* wgate = (const float*)d_in[3];
    const float* wdown = (const float*)d_in[4];
    float* y = (float*)d_out;

    int write_logits = (out_size >= T * H + T * NE) ? 1 : 0;
    float* logits = y + (size_t)T * H;

    cudaFuncSetAttribute(upgate_kernel, cudaFuncAttributeMaxDynamicSharedMemorySize, SMEM_UPGATE);
    cudaFuncSetAttribute(down_kernel,   cudaFuncAttributeMaxDynamicSharedMemorySize, SMEM_DOWN);

    zero_kernel<<<256, 256>>>(y);
    router_kernel<<<T / 4, 128>>>(x, gw, logits, write_logits);
    upgate_kernel<<<dim3(NE * MT, F / 64), 256, SMEM_UPGATE>>>(x, wup, wgate);
    down_kernel<<<dim3(NE * MT, H / 128), 256, SMEM_DOWN>>>(wdown, y);
}

// round 7
// speedup vs baseline: 4.9944x; 1.2671x over previous
#include <cuda_runtime.h>
#include <math.h>
#include <stdint.h>

#define NE 8
#define H 1024
#define F 3584
#define T 4096

#define BM 128
#define BK 32
#define MT (T / BM)

#define AS_STRIDE 36
#define AS_WORDS (BM * AS_STRIDE)   // 4608
#define BU_STRIDE 72
#define BU_WORDS (BK * BU_STRIDE)   // 2304
#define BD_STRIDE 136
#define BD_WORDS (BK * BD_STRIDE)   // 4352

#define SMEM_UPGATE ((2 * AS_WORDS + 4 * BU_WORDS) * 4)   // 73728 B
#define SMEM_DOWN   ((2 * AS_WORDS + 2 * BD_WORDS) * 4)   // 71680 B

// ---------------- scratch (device globals) ----------------
__device__ int      g_count[NE];
__device__ int      g_idx[NE * T];
__device__ float    g_wt[NE * T];
__device__ uint32_t g_act[(size_t)NE * T * F];        // tf32 bits
__device__ uint32_t g_wu_tf[(size_t)NE * H * F];
__device__ uint32_t g_wg_tf[(size_t)NE * H * F];
__device__ uint32_t g_wd_tf[(size_t)NE * F * H];
__device__ uint32_t g_x_tf[(size_t)T * H];

// ---------------- helpers ----------------
__device__ __forceinline__ uint32_t f2tf(float f) {
    uint32_t u;
    asm("cvt.rna.tf32.f32 %0, %1;" : "=r"(u) : "f"(f));
    return u;
}
__device__ __forceinline__ uint32_t smem_u32(const void* p) {
    uint32_t a;
    asm("{ .reg .u64 t; cvta.to.shared.u64 t, %1; cvt.u32.u64 %0, t; }" : "=r"(a) : "l"(p));
    return a;
}
__device__ __forceinline__ void cp16(uint32_t dst, const void* src) {
    asm volatile("cp.async.cg.shared.global [%0], [%1], 16;" :: "r"(dst), "l"(src));
}
#define CP_COMMIT() asm volatile("cp.async.commit_group;" ::: "memory")
#define CP_WAIT1()  asm volatile("cp.async.wait_group 1;" ::: "memory")

__device__ __forceinline__ void mma8(float* d, const uint32_t* a, const uint32_t* b) {
    asm volatile(
        "mma.sync.aligned.m16n8k8.row.col.f32.tf32.tf32.f32 "
        "{%0,%1,%2,%3},{%4,%5,%6,%7},{%8,%9},{%0,%1,%2,%3};"
        : "+f"(d[0]), "+f"(d[1]), "+f"(d[2]), "+f"(d[3])
        : "r"(a[0]), "r"(a[1]), "r"(a[2]), "r"(a[3]), "r"(b[0]), "r"(b[1]));
}

// ---------------- kernel 0: zero y + counters ----------------
__global__ void zero_kernel(float* __restrict__ y) {
    size_t n = (size_t)T * H;
    size_t stride = (size_t)gridDim.x * blockDim.x;
    for (size_t i = (size_t)blockIdx.x * blockDim.x + threadIdx.x; i < n; i += stride)
        y[i] = 0.0f;
    if (blockIdx.x == 0 && threadIdx.x < NE) g_count[threadIdx.x] = 0;
}

// ---------------- kernel: fp32 -> tf32 pre-convert ----------------
__global__ void cvt_kernel(const float4* __restrict__ src, uint4* __restrict__ dst, int n4) {
    int stride = gridDim.x * blockDim.x;
    for (int i = blockIdx.x * blockDim.x + threadIdx.x; i < n4; i += stride) {
        float4 v = src[i];
        uint4 o;
        o.x = f2tf(v.x); o.y = f2tf(v.y); o.z = f2tf(v.z); o.w = f2tf(v.w);
        dst[i] = o;
    }
}

// ---------------- kernel 1: router ----------------
__global__ void router_kernel(const float* __restrict__ x,
                              const float* __restrict__ gw,
                              float* __restrict__ logits_out,
                              int write_logits) {
    int warp = threadIdx.x >> 5;
    int lane = threadIdx.x & 31;
    int t = blockIdx.x * 4 + warp;
    if (t >= T) return;
    const float* xr = x + (size_t)t * H;

    float acc[NE];
#pragma unroll
    for (int e = 0; e < NE; e++) acc[e] = 0.0f;
    for (int k = lane; k < H; k += 32) {
        float xv = xr[k];
        const float* g = gw + (size_t)k * NE;
#pragma unroll
        for (int e = 0; e < NE; e++) acc[e] += xv * g[e];
    }
#pragma unroll
    for (int off = 16; off > 0; off >>= 1)
#pragma unroll
        for (int e = 0; e < NE; e++)
            acc[e] += __shfl_down_sync(0xffffffffu, acc[e], off);

    if (lane == 0) {
        if (write_logits) {
#pragma unroll
            for (int e = 0; e < NE; e++) logits_out[(size_t)t * NE + e] = acc[e];
        }
        int i1 = 0;
#pragma unroll
        for (int e = 1; e < NE; e++) if (acc[e] > acc[i1]) i1 = e;
        int i2 = (i1 == 0) ? 1 : 0;
#pragma unroll
        for (int e = 0; e < NE; e++)
            if (e != i1 && acc[e] > acc[i2]) i2 = e;
        float w1 = 1.0f / (1.0f + expf(acc[i2] - acc[i1]));
        float w2 = 1.0f / (1.0f + expf(acc[i1] - acc[i2]));
        int p1 = atomicAdd(&g_count[i1], 1);
        g_idx[i1 * T + p1] = t; g_wt[i1 * T + p1] = w1;
        int p2 = atomicAdd(&g_count[i2], 1);
        g_idx[i2 * T + p2] = t; g_wt[i2 * T + p2] = w2;
    }
}

// ---------------- kernel 2: cp.async pipelined tf32 up+gate GEMM + SiLU ----------------
// 256 threads, 8 warps (4 row x 2 col), block tile 128x64 (x2 mats), warp tile 32x32.
__global__ __launch_bounds__(256) void upgate_kernel() {
    extern __shared__ uint32_t sm[];
    uint32_t* AsB = sm;                          // [2][BM][36]
    uint32_t* BuB = sm + 2 * AS_WORDS;           // [2][BK][72]
    uint32_t* BgB = BuB + 2 * BU_WORDS;          // [2][BK][72]
    __shared__ int toks[BM];

    int e = blockIdx.x / MT;
    int mtile = blockIdx.x % MT;
    int cnt = g_count[e];
    int row0 = mtile * BM;
    if (row0 >= cnt) return;
    int f0 = blockIdx.y * 64;

    int tid = threadIdx.x;
    if (tid < BM) {
        int r = row0 + tid;
        toks[tid] = (r < cnt) ? g_idx[e * T + r] : g_idx[e * T];  // dup valid token for pad rows
    }
    __syncthreads();

    const uint32_t* Wu = g_wu_tf + (size_t)e * H * F + f0;
    const uint32_t* Wg = g_wg_tf + (size_t)e * H * F + f0;

    uint32_t as_base = smem_u32(AsB);
    uint32_t bu_base = smem_u32(BuB);
    uint32_t bg_base = smem_u32(BgB);

    // cp.async load helpers: A 1024 chunks (4/thread), Bu/Bg 512 chunks each (2/thread)
    auto loadA = [&](int buf, int kn) {
        uint32_t dst = as_base + buf * AS_WORDS * 4;
#pragma unroll
        for (int j = 0; j < 4; j++) {
            int c = tid + j * 256;
            int m = c >> 3, seg = c & 7;
            cp16(dst + (m * AS_STRIDE + seg * 4) * 4,
                 g_x_tf + (size_t)toks[m] * H + kn + seg * 4);
        }
    };
    auto loadB = [&](int buf, int kn) {
        uint32_t du = bu_base + buf * BU_WORDS * 4;
        uint32_t dg = bg_base + buf * BU_WORDS * 4;
#pragma unroll
        for (int j = 0; j < 2; j++) {
            int c = tid + j * 256;
            int kk = c >> 4, seg = c & 15;
            uint32_t off = (kk * BU_STRIDE + seg * 4) * 4;
            size_t gi = (size_t)(kn + kk) * F + seg * 4;
            cp16(du + off, Wu + gi);
            cp16(dg + off, Wg + gi);
        }
    };

    loadA(0, 0); loadB(0, 0); CP_COMMIT();
    loadA(1, BK); loadB(1, BK); CP_COMMIT();

    int wid = tid >> 5, lane = tid & 31;
    int wr = (wid >> 1) * 32;
    int wn = (wid & 1) * 32;
    int qr = lane >> 2, qc = lane & 3;

    float accU[2][4][4], accG[2][4][4];
#pragma unroll
    for (int mt = 0; mt < 2; mt++)
#pragma unroll
        for (int nt = 0; nt < 4; nt++)
#pragma unroll
            for (int i = 0; i < 4; i++) { accU[mt][nt][i] = 0.0f; accG[mt][nt][i] = 0.0f; }

    const int NIT = H / BK;
    for (int i = 0; i < NIT; i++) {
        int b = i & 1;
        CP_WAIT1();
        __syncthreads();

        const uint32_t* Ab = AsB + b * AS_WORDS;
        const uint32_t* Ub = BuB + b * BU_WORDS;
        const uint32_t* Gb = BgB + b * BU_WORDS;
#pragma unroll
        for (int ks = 0; ks < 4; ks++) {
            int c = ks * 8 + qc;
            uint32_t a[2][4], bu[4][2], bg[4][2];
#pragma unroll
            for (int mt = 0; mt < 2; mt++) {
                const uint32_t* ap = Ab + (wr + mt * 16 + qr) * AS_STRIDE + c;
                a[mt][0] = ap[0];
                a[mt][1] = ap[8 * AS_STRIDE];
                a[mt][2] = ap[4];
                a[mt][3] = ap[8 * AS_STRIDE + 4];
            }
#pragma unroll
            for (int nt = 0; nt < 4; nt++) {
                int n = wn + nt * 8 + qr;
                bu[nt][0] = Ub[c * BU_STRIDE + n];
                bu[nt][1] = Ub[(c + 4) * BU_STRIDE + n];
                bg[nt][0] = Gb[c * BU_STRIDE + n];
                bg[nt][1] = Gb[(c + 4) * BU_STRIDE + n];
            }
#pragma unroll
            for (int mt = 0; mt < 2; mt++)
#pragma unroll
                for (int nt = 0; nt < 4; nt++) {
                    mma8(accU[mt][nt], a[mt], bu[nt]);
                    mma8(accG[mt][nt], a[mt], bg[nt]);
                }
        }
        __syncthreads();
        if (i + 2 < NIT) {
            int kn = (i + 2) * BK;
            loadA(b, kn); loadB(b, kn);
        }
        CP_COMMIT();
    }

    // epilogue: silu(up)*gate -> g_act as tf32 bits
#pragma unroll
    for (int mt = 0; mt < 2; mt++)
#pragma unroll
        for (int nt = 0; nt < 4; nt++) {
            int col = f0 + wn + nt * 8 + 2 * qc;
#pragma unroll
            for (int h = 0; h < 2; h++) {
                int r = row0 + wr + mt * 16 + qr + h * 8;
                if (r >= cnt) continue;
                float u0 = accU[mt][nt][h * 2 + 0], u1 = accU[mt][nt][h * 2 + 1];
                float g0 = accG[mt][nt][h * 2 + 0], g1 = accG[mt][nt][h * 2 + 1];
                float s0 = u0 / (1.0f + expf(-u0)) * g0;
                float s1 = u1 / (1.0f + expf(-u1)) * g1;
                uint2 o; o.x = f2tf(s0); o.y = f2tf(s1);
                *(uint2*)(g_act + ((size_t)e * T + r) * F + col) = o;
            }
        }
}

// ---------------- kernel 3: cp.async pipelined tf32 down GEMM + weighted scatter ----------------
// 256 threads, 8 warps (4 row x 2 col), block tile 128x128, warp tile 32x64.
__global__ __launch_bounds__(256) void down_kernel(float* __restrict__ y) {
    extern __shared__ uint32_t sm[];
    uint32_t* AsB = sm;                 // [2][BM][36]
    uint32_t* BsB = sm + 2 * AS_WORDS;  // [2][BK][136]

    int e = blockIdx.x / MT;
    int mtile = blockIdx.x % MT;
    int cnt = g_count[e];
    int row0 = mtile * BM;
    if (row0 >= cnt) return;
    int n0 = blockIdx.y * 128;

    const uint32_t* A = g_act + ((size_t)e * T + row0) * F;   // tf32 bits, rows >= cnt are junk but row-local
    const uint32_t* W = g_wd_tf + (size_t)e * F * H + n0;

    int tid = threadIdx.x;
    uint32_t as_base = smem_u32(AsB);
    uint32_t bs_base = smem_u32(BsB);

    auto loadA = [&](int buf, int kn) {
        uint32_t dst = as_base + buf * AS_WORDS * 4;
#pragma unroll
        for (int j = 0; j < 4; j++) {
            int c = tid + j * 256;
            int m = c >> 3, seg = c & 7;
            cp16(dst + (m * AS_STRIDE + seg * 4) * 4,
                 A + (size_t)m * F + kn + seg * 4);
        }
    };
    auto loadB = [&](int buf, int kn) {
        uint32_t dst = bs_base + buf * BD_WORDS * 4;
#pragma unroll
        for (int j = 0; j < 4; j++) {
            int c = tid + j * 256;
            int kk = c >> 5, seg = c & 31;
            cp16(dst + (kk * BD_STRIDE + seg * 4) * 4,
                 W + (size_t)(kn + kk) * H + seg * 4);
        }
    };

    loadA(0, 0); loadB(0, 0); CP_COMMIT();
    loadA(1, BK); loadB(1, BK); CP_COMMIT();

    int wid = tid >> 5, lane = tid & 31;
    int wr = (wid >> 1) * 32;
    int wn = (wid & 1) * 64;
    int qr = lane >> 2, qc = lane & 3;

    float acc[2][8][4];
#pragma unroll
    for (int mt = 0; mt < 2; mt++)
#pragma unroll
        for (int nt = 0; nt < 8; nt++)
#pragma unroll
            for (int i = 0; i < 4; i++) acc[mt][nt][i] = 0.0f;

    const int NIT = F / BK;
    for (int i = 0; i < NIT; i++) {
        int b = i & 1;
        CP_WAIT1();
        __syncthreads();

        const uint32_t* Ab = AsB + b * AS_WORDS;
        const uint32_t* Bb = BsB + b * BD_WORDS;
#pragma unroll
        for (int ks = 0; ks < 4; ks++) {
            int c = ks * 8 + qc;
            uint32_t a[2][4], bfr[8][2];
#pragma unroll
            for (int mt = 0; mt < 2; mt++) {
                const uint32_t* ap = Ab + (wr + mt * 16 + qr) * AS_STRIDE + c;
                a[mt][0] = ap[0];
                a[mt][1] = ap[8 * AS_STRIDE];
                a[mt][2] = ap[4];
                a[mt][3] = ap[8 * AS_STRIDE + 4];
            }
#pragma unroll
            for (int nt = 0; nt < 8; nt++) {
                int n = wn + nt * 8 + qr;
                bfr[nt][0] = Bb[c * BD_STRIDE + n];
                bfr[nt][1] = Bb[(c + 4) * BD_STRIDE + n];
            }
#pragma unroll
            for (int mt = 0; mt < 2; mt++)
#pragma unroll
                for (int nt = 0; nt < 8; nt++)
                    mma8(acc[mt][nt], a[mt], bfr[nt]);
        }
        __syncthreads();
        if (i + 2 < NIT) {
            int kn = (i + 2) * BK;
            loadA(b, kn); loadB(b, kn);
        }
        CP_COMMIT();
    }

    // weighted scatter
#pragma unroll
    for (int mt = 0; mt < 2; mt++)
#pragma unroll
        for (int nt = 0; nt < 8; nt++) {
            int col = n0 + wn + nt * 8 + 2 * qc;
#pragma unroll
            for (int h = 0; h < 2; h++) {
                int r = row0 + wr + mt * 16 + qr + h * 8;
                if (r >= cnt) continue;
                int tok = g_idx[e * T + r];
                float wgt = g_wt[e * T + r];
                float* yr = y + (size_t)tok * H + col;
                atomicAdd(&yr[0], acc[mt][nt][h * 2 + 0] * wgt);
                atomicAdd(&yr[1], acc[mt][nt][h * 2 + 1] * wgt);
            }
        }
}

// ---------------- launch ----------------
extern "C" void kernel_launch(void* const* d_in, const int* in_sizes, int n_in,
                              void* d_out, int out_size) {
    const float* x     = (const float*)d_in[0];
    const float* gw    = (const float*)d_in[1];
    const float* wup   = (const float*)d_in[2];
    const float* wgate = (const float*)d_in[3];
    const float* wdown = (const float*)d_in[4];
    float* y = (float*)d_out;

    int write_logits = (out_size >= T * H + T * NE) ? 1 : 0;
    float* logits = y + (size_t)T * H;

    uint32_t *wu_tf, *wg_tf, *wd_tf, *x_tf;
    cudaGetSymbolAddress((void**)&wu_tf, g_wu_tf);
    cudaGetSymbolAddress((void**)&wg_tf, g_wg_tf);
    cudaGetSymbolAddress((void**)&wd_tf, g_wd_tf);
    cudaGetSymbolAddress((void**)&x_tf, g_x_tf);

    cudaFuncSetAttribute(upgate_kernel, cudaFuncAttributeMaxDynamicSharedMemorySize, SMEM_UPGATE);
    cudaFuncSetAttribute(down_kernel,   cudaFuncAttributeMaxDynamicSharedMemorySize, SMEM_DOWN);

    zero_kernel<<<256, 256>>>(y);
    int nw = NE * H * F / 4;
    cvt_kernel<<<2048, 256>>>((const float4*)wup,   (uint4*)wu_tf, nw);
    cvt_kernel<<<2048, 256>>>((const float4*)wgate, (uint4*)wg_tf, nw);
    cvt_kernel<<<2048, 256>>>((const float4*)wdown, (uint4*)wd_tf, nw);
    cvt_kernel<<<512, 256>>>((const float4*)x, (uint4*)x_tf, T * H / 4);
    router_kernel<<<T / 4, 128>>>(x, gw, logits, write_logits);
    upgate_kernel<<<dim3(NE * MT, F / 64), 256, SMEM_UPGATE>>>();
    down_kernel<<<dim3(NE * MT, H / 128), 256, SMEM_DOWN>>>(y);
}

// round 8
// speedup vs baseline: 5.1508x; 1.0313x over previous
#include <cuda_runtime.h>
#include <math.h>
#include <stdint.h>

#define NE 8
#define H 1024
#define F 3584
#define T 4096

#define BM 128
#define BK 32
#define MT (T / BM)

#define AS_STRIDE 36
#define AS_WORDS (BM * AS_STRIDE)   // 4608
#define BU_STRIDE 72
#define BU_WORDS (BK * BU_STRIDE)   // 2304
#define BD_STRIDE 136
#define BD_WORDS (BK * BD_STRIDE)   // 4352

#define SMEM_UPGATE ((2 * AS_WORDS + 4 * BU_WORDS) * 4)   // 73728 B
#define SMEM_DOWN   ((2 * AS_WORDS + 2 * BD_WORDS) * 4)   // 71680 B

// ---------------- scratch (device globals) ----------------
__device__ int      g_count[NE];
__device__ int      g_idx[NE * T];
__device__ float    g_wt[NE * T];
__device__ uint32_t g_act[(size_t)NE * T * F];        // tf32 bits
__device__ uint32_t g_wu_tf[(size_t)NE * H * F];
__device__ uint32_t g_wg_tf[(size_t)NE * H * F];
__device__ uint32_t g_wd_tf[(size_t)NE * F * H];
__device__ uint32_t g_x_tf[(size_t)T * H];

// ---------------- helpers ----------------
__device__ __forceinline__ uint32_t f2tf(float f) {
    uint32_t u;
    asm("cvt.rna.tf32.f32 %0, %1;" : "=r"(u) : "f"(f));
    return u;
}
__device__ __forceinline__ uint32_t smem_u32(const void* p) {
    uint32_t a;
    asm("{ .reg .u64 t; cvta.to.shared.u64 t, %1; cvt.u32.u64 %0, t; }" : "=r"(a) : "l"(p));
    return a;
}
__device__ __forceinline__ void cp16(uint32_t dst, const void* src) {
    asm volatile("cp.async.cg.shared.global [%0], [%1], 16;" :: "r"(dst), "l"(src));
}
#define CP_COMMIT() asm volatile("cp.async.commit_group;" ::: "memory")
#define CP_WAIT1()  asm volatile("cp.async.wait_group 1;" ::: "memory")

__device__ __forceinline__ void mma8(float* d, const uint32_t* a, const uint32_t* b) {
    asm volatile(
        "mma.sync.aligned.m16n8k8.row.col.f32.tf32.tf32.f32 "
        "{%0,%1,%2,%3},{%4,%5,%6,%7},{%8,%9},{%0,%1,%2,%3};"
        : "+f"(d[0]), "+f"(d[1]), "+f"(d[2]), "+f"(d[3])
        : "r"(a[0]), "r"(a[1]), "r"(a[2]), "r"(a[3]), "r"(b[0]), "r"(b[1]));
}

// ---------------- kernel 0: zero y + counters ----------------
__global__ void zero_kernel(float* __restrict__ y) {
    size_t n = (size_t)T * H;
    size_t stride = (size_t)gridDim.x * blockDim.x;
    for (size_t i = (size_t)blockIdx.x * blockDim.x + threadIdx.x; i < n; i += stride)
        y[i] = 0.0f;
    if (blockIdx.x == 0 && threadIdx.x < NE) g_count[threadIdx.x] = 0;
}

// ---------------- kernel: fp32 -> tf32 pre-convert ----------------
__global__ void cvt_kernel(const float4* __restrict__ src, uint4* __restrict__ dst, int n4) {
    int stride = gridDim.x * blockDim.x;
    for (int i = blockIdx.x * blockDim.x + threadIdx.x; i < n4; i += stride) {
        float4 v = src[i];
        uint4 o;
        o.x = f2tf(v.x); o.y = f2tf(v.y); o.z = f2tf(v.z); o.w = f2tf(v.w);
        dst[i] = o;
    }
}

// ---------------- kernel 1: router ----------------
__global__ void router_kernel(const float* __restrict__ x,
                              const float* __restrict__ gw,
                              float* __restrict__ logits_out,
                              int write_logits) {
    int warp = threadIdx.x >> 5;
    int lane = threadIdx.x & 31;
    int t = blockIdx.x * 4 + warp;
    if (t >= T) return;
    const float* xr = x + (size_t)t * H;

    float acc[NE];
#pragma unroll
    for (int e = 0; e < NE; e++) acc[e] = 0.0f;
    for (int k = lane; k < H; k += 32) {
        float xv = xr[k];
        const float* g = gw + (size_t)k * NE;
#pragma unroll
        for (int e = 0; e < NE; e++) acc[e] += xv * g[e];
    }
#pragma unroll
    for (int off = 16; off > 0; off >>= 1)
#pragma unroll
        for (int e = 0; e < NE; e++)
            acc[e] += __shfl_down_sync(0xffffffffu, acc[e], off);

    if (lane == 0) {
        if (write_logits) {
#pragma unroll
            for (int e = 0; e < NE; e++) logits_out[(size_t)t * NE + e] = acc[e];
        }
        int i1 = 0;
#pragma unroll
        for (int e = 1; e < NE; e++) if (acc[e] > acc[i1]) i1 = e;
        int i2 = (i1 == 0) ? 1 : 0;
#pragma unroll
        for (int e = 0; e < NE; e++)
            if (e != i1 && acc[e] > acc[i2]) i2 = e;
        float w1 = 1.0f / (1.0f + expf(acc[i2] - acc[i1]));
        float w2 = 1.0f / (1.0f + expf(acc[i1] - acc[i2]));
        int p1 = atomicAdd(&g_count[i1], 1);
        g_idx[i1 * T + p1] = t; g_wt[i1 * T + p1] = w1;
        int p2 = atomicAdd(&g_count[i2], 1);
        g_idx[i2 * T + p2] = t; g_wt[i2 * T + p2] = w2;
    }
}

// ---------------- kernel 2: cp.async pipelined tf32 up+gate GEMM + SiLU ----------------
// 256 threads, 8 warps (4 row x 2 col), block tile 128x64 (x2 mats), warp tile 32x32.
// 2 CTAs/SM co-residency to hide barrier/LDS/epilogue latency.
__global__ __launch_bounds__(256, 2) void upgate_kernel() {
    extern __shared__ uint32_t sm[];
    uint32_t* AsB = sm;                          // [2][BM][36]
    uint32_t* BuB = sm + 2 * AS_WORDS;           // [2][BK][72]
    uint32_t* BgB = BuB + 2 * BU_WORDS;          // [2][BK][72]
    __shared__ int toks[BM];

    int e = blockIdx.x / MT;
    int mtile = blockIdx.x % MT;
    int cnt = g_count[e];
    int row0 = mtile * BM;
    if (row0 >= cnt) return;
    int f0 = blockIdx.y * 64;

    int tid = threadIdx.x;
    if (tid < BM) {
        int r = row0 + tid;
        toks[tid] = (r < cnt) ? g_idx[e * T + r] : g_idx[e * T];  // dup valid token for pad rows
    }
    __syncthreads();

    const uint32_t* Wu = g_wu_tf + (size_t)e * H * F + f0;
    const uint32_t* Wg = g_wg_tf + (size_t)e * H * F + f0;

    uint32_t as_base = smem_u32(AsB);
    uint32_t bu_base = smem_u32(BuB);
    uint32_t bg_base = smem_u32(BgB);

    auto loadA = [&](int buf, int kn) {
        uint32_t dst = as_base + buf * AS_WORDS * 4;
#pragma unroll
        for (int j = 0; j < 4; j++) {
            int c = tid + j * 256;
            int m = c >> 3, seg = c & 7;
            cp16(dst + (m * AS_STRIDE + seg * 4) * 4,
                 g_x_tf + (size_t)toks[m] * H + kn + seg * 4);
        }
    };
    auto loadB = [&](int buf, int kn) {
        uint32_t du = bu_base + buf * BU_WORDS * 4;
        uint32_t dg = bg_base + buf * BU_WORDS * 4;
#pragma unroll
        for (int j = 0; j < 2; j++) {
            int c = tid + j * 256;
            int kk = c >> 4, seg = c & 15;
            uint32_t off = (kk * BU_STRIDE + seg * 4) * 4;
            size_t gi = (size_t)(kn + kk) * F + seg * 4;
            cp16(du + off, Wu + gi);
            cp16(dg + off, Wg + gi);
        }
    };

    loadA(0, 0); loadB(0, 0); CP_COMMIT();
    loadA(1, BK); loadB(1, BK); CP_COMMIT();

    int wid = tid >> 5, lane = tid & 31;
    int wr = (wid >> 1) * 32;
    int wn = (wid & 1) * 32;
    int qr = lane >> 2, qc = lane & 3;

    float accU[2][4][4], accG[2][4][4];
#pragma unroll
    for (int mt = 0; mt < 2; mt++)
#pragma unroll
        for (int nt = 0; nt < 4; nt++)
#pragma unroll
            for (int i = 0; i < 4; i++) { accU[mt][nt][i] = 0.0f; accG[mt][nt][i] = 0.0f; }

    const int NIT = H / BK;
    for (int i = 0; i < NIT; i++) {
        int b = i & 1;
        CP_WAIT1();
        __syncthreads();

        const uint32_t* Ab = AsB + b * AS_WORDS;
        const uint32_t* Ub = BuB + b * BU_WORDS;
        const uint32_t* Gb = BgB + b * BU_WORDS;
#pragma unroll
        for (int ks = 0; ks < 4; ks++) {
            int c = ks * 8 + qc;
            uint32_t a[2][4], bu[4][2], bg[4][2];
#pragma unroll
            for (int mt = 0; mt < 2; mt++) {
                const uint32_t* ap = Ab + (wr + mt * 16 + qr) * AS_STRIDE + c;
                a[mt][0] = ap[0];
                a[mt][1] = ap[8 * AS_STRIDE];
                a[mt][2] = ap[4];
                a[mt][3] = ap[8 * AS_STRIDE + 4];
            }
#pragma unroll
            for (int nt = 0; nt < 4; nt++) {
                int n = wn + nt * 8 + qr;
                bu[nt][0] = Ub[c * BU_STRIDE + n];
                bu[nt][1] = Ub[(c + 4) * BU_STRIDE + n];
                bg[nt][0] = Gb[c * BU_STRIDE + n];
                bg[nt][1] = Gb[(c + 4) * BU_STRIDE + n];
            }
#pragma unroll
            for (int mt = 0; mt < 2; mt++)
#pragma unroll
                for (int nt = 0; nt < 4; nt++) {
                    mma8(accU[mt][nt], a[mt], bu[nt]);
                    mma8(accG[mt][nt], a[mt], bg[nt]);
                }
        }
        __syncthreads();
        if (i + 2 < NIT) {
            int kn = (i + 2) * BK;
            loadA(b, kn); loadB(b, kn);
        }
        CP_COMMIT();
    }

    // epilogue: silu(up)*gate -> g_act as tf32 bits
#pragma unroll
    for (int mt = 0; mt < 2; mt++)
#pragma unroll
        for (int nt = 0; nt < 4; nt++) {
            int col = f0 + wn + nt * 8 + 2 * qc;
#pragma unroll
            for (int h = 0; h < 2; h++) {
                int r = row0 + wr + mt * 16 + qr + h * 8;
                if (r >= cnt) continue;
                float u0 = accU[mt][nt][h * 2 + 0], u1 = accU[mt][nt][h * 2 + 1];
                float g0 = accG[mt][nt][h * 2 + 0], g1 = accG[mt][nt][h * 2 + 1];
                float s0 = u0 / (1.0f + expf(-u0)) * g0;
                float s1 = u1 / (1.0f + expf(-u1)) * g1;
                uint2 o; o.x = f2tf(s0); o.y = f2tf(s1);
                *(uint2*)(g_act + ((size_t)e * T + r) * F + col) = o;
            }
        }
}

// ---------------- kernel 3: cp.async pipelined tf32 down GEMM + weighted scatter ----------------
// 256 threads, 8 warps (4 row x 2 col), block tile 128x128, warp tile 32x64. 2 CTAs/SM.
__global__ __launch_bounds__(256, 2) void down_kernel(float* __restrict__ y) {
    extern __shared__ uint32_t sm[];
    uint32_t* AsB = sm;                 // [2][BM][36]
    uint32_t* BsB = sm + 2 * AS_WORDS;  // [2][BK][136]

    int e = blockIdx.x / MT;
    int mtile = blockIdx.x % MT;
    int cnt = g_count[e];
    int row0 = mtile * BM;
    if (row0 >= cnt) return;
    int n0 = blockIdx.y * 128;

    const uint32_t* A = g_act + ((size_t)e * T + row0) * F;
    const uint32_t* W = g_wd_tf + (size_t)e * F * H + n0;

    int tid = threadIdx.x;
    uint32_t as_base = smem_u32(AsB);
    uint32_t bs_base = smem_u32(BsB);

    auto loadA = [&](int buf, int kn) {
        uint32_t dst = as_base + buf * AS_WORDS * 4;
#pragma unroll
        for (int j = 0; j < 4; j++) {
            int c = tid + j * 256;
            int m = c >> 3, seg = c & 7;
            cp16(dst + (m * AS_STRIDE + seg * 4) * 4,
                 A + (size_t)m * F + kn + seg * 4);
        }
    };
    auto loadB = [&](int buf, int kn) {
        uint32_t dst = bs_base + buf * BD_WORDS * 4;
#pragma unroll
        for (int j = 0; j < 4; j++) {
            int c = tid + j * 256;
            int kk = c >> 5, seg = c & 31;
            cp16(dst + (kk * BD_STRIDE + seg * 4) * 4,
                 W + (size_t)(kn + kk) * H + seg * 4);
        }
    };

    loadA(0, 0); loadB(0, 0); CP_COMMIT();
    loadA(1, BK); loadB(1, BK); CP_COMMIT();

    int wid = tid >> 5, lane = tid & 31;
    int wr = (wid >> 1) * 32;
    int wn = (wid & 1) * 64;
    int qr = lane >> 2, qc = lane & 3;

    float acc[2][8][4];
#pragma unroll
    for (int mt = 0; mt < 2; mt++)
#pragma unroll
        for (int nt = 0; nt < 8; nt++)
#pragma unroll
            for (int i = 0; i < 4; i++) acc[mt][nt][i] = 0.0f;

    const int NIT = F / BK;
    for (int i = 0; i < NIT; i++) {
        int b = i & 1;
        CP_WAIT1();
        __syncthreads();

        const uint32_t* Ab = AsB + b * AS_WORDS;
        const uint32_t* Bb = BsB + b * BD_WORDS;
#pragma unroll
        for (int ks = 0; ks < 4; ks++) {
            int c = ks * 8 + qc;
            uint32_t a[2][4], bfr[8][2];
#pragma unroll
            for (int mt = 0; mt < 2; mt++) {
                const uint32_t* ap = Ab + (wr + mt * 16 + qr) * AS_STRIDE + c;
                a[mt][0] = ap[0];
                a[mt][1] = ap[8 * AS_STRIDE];
                a[mt][2] = ap[4];
                a[mt][3] = ap[8 * AS_STRIDE + 4];
            }
#pragma unroll
            for (int nt = 0; nt < 8; nt++) {
                int n = wn + nt * 8 + qr;
                bfr[nt][0] = Bb[c * BD_STRIDE + n];
                bfr[nt][1] = Bb[(c + 4) * BD_STRIDE + n];
            }
#pragma unroll
            for (int mt = 0; mt < 2; mt++)
#pragma unroll
                for (int nt = 0; nt < 8; nt++)
                    mma8(acc[mt][nt], a[mt], bfr[nt]);
        }
        __syncthreads();
        if (i + 2 < NIT) {
            int kn = (i + 2) * BK;
            loadA(b, kn); loadB(b, kn);
        }
        CP_COMMIT();
    }

    // weighted scatter
#pragma unroll
    for (int mt = 0; mt < 2; mt++)
#pragma unroll
        for (int nt = 0; nt < 8; nt++) {
            int col = n0 + wn + nt * 8 + 2 * qc;
#pragma unroll
            for (int h = 0; h < 2; h++) {
                int r = row0 + wr + mt * 16 + qr + h * 8;
                if (r >= cnt) continue;
                int tok = g_idx[e * T + r];
                float wgt = g_wt[e * T + r];
                float* yr = y + (size_t)tok * H + col;
                atomicAdd(&yr[0], acc[mt][nt][h * 2 + 0] * wgt);
                atomicAdd(&yr[1], acc[mt][nt][h * 2 + 1] * wgt);
            }
        }
}

// ---------------- launch ----------------
extern "C" void kernel_launch(void* const* d_in, const int* in_sizes, int n_in,
                              void* d_out, int out_size) {
    const float* x     = (const float*)d_in[0];
    const float* gw    = (const float*)d_in[1];
    const float* wup   = (const float*)d_in[2];
    const float* wgate = (const float*)d_in[3];
    const float* wdown = (const float*)d_in[4];
    float* y = (float*)d_out;

    int write_logits = (out_size >= T * H + T * NE) ? 1 : 0;
    float* logits = y + (size_t)T * H;

    uint32_t *wu_tf, *wg_tf, *wd_tf, *x_tf;
    cudaGetSymbolAddress((void**)&wu_tf, g_wu_tf);
    cudaGetSymbolAddress((void**)&wg_tf, g_wg_tf);
    cudaGetSymbolAddress((void**)&wd_tf, g_wd_tf);
    cudaGetSymbolAddress((void**)&x_tf, g_x_tf);

    cudaFuncSetAttribute(upgate_kernel, cudaFuncAttributeMaxDynamicSharedMemorySize, SMEM_UPGATE);
    cudaFuncSetAttribute(down_kernel,   cudaFuncAttributeMaxDynamicSharedMemorySize, SMEM_DOWN);

    zero_kernel<<<256, 256>>>(y);
    int nw = NE * H * F / 4;
    cvt_kernel<<<2048, 256>>>((const float4*)wup,   (uint4*)wu_tf, nw);
    cvt_kernel<<<2048, 256>>>((const float4*)wgate, (uint4*)wg_tf, nw);
    cvt_kernel<<<2048, 256>>>((const float4*)wdown, (uint4*)wd_tf, nw);
    cvt_kernel<<<512, 256>>>((const float4*)x, (uint4*)x_tf, T * H / 4);
    router_kernel<<<T / 4, 128>>>(x, gw, logits, write_logits);
    upgate_kernel<<<dim3(NE * MT, F / 64), 256, SMEM_UPGATE>>>();
    down_kernel<<<dim3(NE * MT, H / 128), 256, SMEM_DOWN>>>(y);
}

// round 9
// speedup vs baseline: 5.3471x; 1.0381x over previous
#include <cuda_runtime.h>
#include <math.h>
#include <stdint.h>

#define NE 8
#define H 1024
#define F 3584
#define T 4096

#define BM 128
#define BK 32
#define MT (T / BM)

#define AS_STRIDE 36
#define AS_WORDS (BM * AS_STRIDE)   // 4608
#define BU_STRIDE 72
#define BU_WORDS (BK * BU_STRIDE)   // 2304
#define BD_STRIDE 136
#define BD_WORDS (BK * BD_STRIDE)   // 4352

#define SMEM_UPGATE ((2 * AS_WORDS + 4 * BU_WORDS) * 4)   // 73728 B
#define SMEM_DOWN   ((2 * AS_WORDS + 2 * BD_WORDS) * 4)   // 71680 B

// ---------------- scratch (device globals) ----------------
__device__ int      g_count[NE];
__device__ int      g_idx[NE * T];
__device__ float    g_wt[NE * T];
__device__ uint32_t g_act[(size_t)NE * T * F];        // tf32 bits
__device__ uint32_t g_wu_tf[(size_t)NE * H * F];
__device__ uint32_t g_wg_tf[(size_t)NE * H * F];
__device__ uint32_t g_wd_tf[(size_t)NE * F * H];
__device__ uint32_t g_x_tf[(size_t)T * H];

// ---------------- helpers ----------------
__device__ __forceinline__ uint32_t f2tf(float f) {
    uint32_t u;
    asm("cvt.rna.tf32.f32 %0, %1;" : "=r"(u) : "f"(f));
    return u;
}
__device__ __forceinline__ uint32_t smem_u32(const void* p) {
    uint32_t a;
    asm("{ .reg .u64 t; cvta.to.shared.u64 t, %1; cvt.u32.u64 %0, t; }" : "=r"(a) : "l"(p));
    return a;
}
__device__ __forceinline__ void cp16(uint32_t dst, const void* src) {
    asm volatile("cp.async.cg.shared.global [%0], [%1], 16;" :: "r"(dst), "l"(src));
}
#define CP_COMMIT() asm volatile("cp.async.commit_group;" ::: "memory")
#define CP_WAIT1()  asm volatile("cp.async.wait_group 1;" ::: "memory")

__device__ __forceinline__ void mma8(float* d, const uint32_t* a, const uint32_t* b) {
    asm volatile(
        "mma.sync.aligned.m16n8k8.row.col.f32.tf32.tf32.f32 "
        "{%0,%1,%2,%3},{%4,%5,%6,%7},{%8,%9},{%0,%1,%2,%3};"
        : "+f"(d[0]), "+f"(d[1]), "+f"(d[2]), "+f"(d[3])
        : "r"(a[0]), "r"(a[1]), "r"(a[2]), "r"(a[3]), "r"(b[0]), "r"(b[1]));
}

// ---------------- kernel 0: zero y + counters ----------------
__global__ void zero_kernel(float* __restrict__ y) {
    size_t n = (size_t)T * H;
    size_t stride = (size_t)gridDim.x * blockDim.x;
    for (size_t i = (size_t)blockIdx.x * blockDim.x + threadIdx.x; i < n; i += stride)
        y[i] = 0.0f;
    if (blockIdx.x == 0 && threadIdx.x < NE) g_count[threadIdx.x] = 0;
}

// ---------------- kernel: fp32 -> tf32 pre-convert ----------------
__global__ void cvt_kernel(const float4* __restrict__ src, uint4* __restrict__ dst, int n4) {
    int stride = gridDim.x * blockDim.x;
    for (int i = blockIdx.x * blockDim.x + threadIdx.x; i < n4; i += stride) {
        float4 v = src[i];
        uint4 o;
        o.x = f2tf(v.x); o.y = f2tf(v.y); o.z = f2tf(v.z); o.w = f2tf(v.w);
        dst[i] = o;
    }
}

// ---------------- kernel 1: router ----------------
__global__ void router_kernel(const float* __restrict__ x,
                              const float* __restrict__ gw,
                              float* __restrict__ logits_out,
                              int write_logits) {
    int warp = threadIdx.x >> 5;
    int lane = threadIdx.x & 31;
    int t = blockIdx.x * 4 + warp;
    if (t >= T) return;
    const float* xr = x + (size_t)t * H;

    float acc[NE];
#pragma unroll
    for (int e = 0; e < NE; e++) acc[e] = 0.0f;
    for (int k = lane; k < H; k += 32) {
        float xv = xr[k];
        const float* g = gw + (size_t)k * NE;
#pragma unroll
        for (int e = 0; e < NE; e++) acc[e] += xv * g[e];
    }
#pragma unroll
    for (int off = 16; off > 0; off >>= 1)
#pragma unroll
        for (int e = 0; e < NE; e++)
            acc[e] += __shfl_down_sync(0xffffffffu, acc[e], off);

    if (lane == 0) {
        if (write_logits) {
#pragma unroll
            for (int e = 0; e < NE; e++) logits_out[(size_t)t * NE + e] = acc[e];
        }
        int i1 = 0;
#pragma unroll
        for (int e = 1; e < NE; e++) if (acc[e] > acc[i1]) i1 = e;
        int i2 = (i1 == 0) ? 1 : 0;
#pragma unroll
        for (int e = 0; e < NE; e++)
            if (e != i1 && acc[e] > acc[i2]) i2 = e;
        float w1 = 1.0f / (1.0f + expf(acc[i2] - acc[i1]));
        float w2 = 1.0f / (1.0f + expf(acc[i1] - acc[i2]));
        int p1 = atomicAdd(&g_count[i1], 1);
        g_idx[i1 * T + p1] = t; g_wt[i1 * T + p1] = w1;
        int p2 = atomicAdd(&g_count[i2], 1);
        g_idx[i2 * T + p2] = t; g_wt[i2 * T + p2] = w2;
    }
}

// ---------------- kernel 2: tf32 up+gate GEMM + SiLU ----------------
// 128 threads, 4 warps (2 row x 2 col), block tile 128x64 (x2 mats),
// warp tile 64x32 per matrix. cp.async double buffer. 2 CTAs/SM.
__global__ __launch_bounds__(128, 2) void upgate_kernel() {
    extern __shared__ uint32_t sm[];
    uint32_t* AsB = sm;                          // [2][BM][36]
    uint32_t* BuB = sm + 2 * AS_WORDS;           // [2][BK][72]
    uint32_t* BgB = BuB + 2 * BU_WORDS;          // [2][BK][72]
    __shared__ int toks[BM];

    int e = blockIdx.x / MT;
    int mtile = blockIdx.x % MT;
    int cnt = g_count[e];
    int row0 = mtile * BM;
    if (row0 >= cnt) return;
    int f0 = blockIdx.y * 64;

    int tid = threadIdx.x;
    if (tid < BM) {
        int r = row0 + tid;
        toks[tid] = (r < cnt) ? g_idx[e * T + r] : g_idx[e * T];
    }
    __syncthreads();

    const uint32_t* Wu = g_wu_tf + (size_t)e * H * F + f0;
    const uint32_t* Wg = g_wg_tf + (size_t)e * H * F + f0;

    uint32_t as_base = smem_u32(AsB);
    uint32_t bu_base = smem_u32(BuB);
    uint32_t bg_base = smem_u32(BgB);

    // A: 128x32 words = 1024 16B-chunks -> 8/thread. Bu/Bg: 32x64 = 512 chunks -> 4/thread each.
    auto loadA = [&](int buf, int kn) {
        uint32_t dst = as_base + buf * AS_WORDS * 4;
#pragma unroll
        for (int j = 0; j < 8; j++) {
            int c = tid + j * 128;
            int m = c >> 3, seg = c & 7;
            cp16(dst + (m * AS_STRIDE + seg * 4) * 4,
                 g_x_tf + (size_t)toks[m] * H + kn + seg * 4);
        }
    };
    auto loadB = [&](int buf, int kn) {
        uint32_t du = bu_base + buf * BU_WORDS * 4;
        uint32_t dg = bg_base + buf * BU_WORDS * 4;
#pragma unroll
        for (int j = 0; j < 4; j++) {
            int c = tid + j * 128;
            int kk = c >> 4, seg = c & 15;
            uint32_t off = (kk * BU_STRIDE + seg * 4) * 4;
            size_t gi = (size_t)(kn + kk) * F + seg * 4;
            cp16(du + off, Wu + gi);
            cp16(dg + off, Wg + gi);
        }
    };

    loadA(0, 0); loadB(0, 0); CP_COMMIT();
    loadA(1, BK); loadB(1, BK); CP_COMMIT();

    int wid = tid >> 5, lane = tid & 31;
    int wr = (wid >> 1) * 64;     // warp row: 0 or 64
    int wn = (wid & 1) * 32;      // warp col: 0 or 32
    int qr = lane >> 2, qc = lane & 3;

    float accU[4][4][4], accG[4][4][4];
#pragma unroll
    for (int mt = 0; mt < 4; mt++)
#pragma unroll
        for (int nt = 0; nt < 4; nt++)
#pragma unroll
            for (int i = 0; i < 4; i++) { accU[mt][nt][i] = 0.0f; accG[mt][nt][i] = 0.0f; }

    const int NIT = H / BK;
    for (int i = 0; i < NIT; i++) {
        int b = i & 1;
        CP_WAIT1();
        __syncthreads();

        const uint32_t* Ab = AsB + b * AS_WORDS;
        const uint32_t* Ub = BuB + b * BU_WORDS;
        const uint32_t* Gb = BgB + b * BU_WORDS;
#pragma unroll
        for (int ks = 0; ks < 4; ks++) {
            int c = ks * 8 + qc;
            uint32_t a[4][4], bu[4][2], bg[4][2];
#pragma unroll
            for (int mt = 0; mt < 4; mt++) {
                const uint32_t* ap = Ab + (wr + mt * 16 + qr) * AS_STRIDE + c;
                a[mt][0] = ap[0];
                a[mt][1] = ap[8 * AS_STRIDE];
                a[mt][2] = ap[4];
                a[mt][3] = ap[8 * AS_STRIDE + 4];
            }
#pragma unroll
            for (int nt = 0; nt < 4; nt++) {
                int n = wn + nt * 8 + qr;
                bu[nt][0] = Ub[c * BU_STRIDE + n];
                bu[nt][1] = Ub[(c + 4) * BU_STRIDE + n];
                bg[nt][0] = Gb[c * BU_STRIDE + n];
                bg[nt][1] = Gb[(c + 4) * BU_STRIDE + n];
            }
#pragma unroll
            for (int mt = 0; mt < 4; mt++)
#pragma unroll
                for (int nt = 0; nt < 4; nt++) {
                    mma8(accU[mt][nt], a[mt], bu[nt]);
                    mma8(accG[mt][nt], a[mt], bg[nt]);
                }
        }
        __syncthreads();
        if (i + 2 < NIT) {
            int kn = (i + 2) * BK;
            loadA(b, kn); loadB(b, kn);
        }
        CP_COMMIT();
    }

    // epilogue: silu(up)*gate -> g_act as tf32 bits
#pragma unroll
    for (int mt = 0; mt < 4; mt++)
#pragma unroll
        for (int nt = 0; nt < 4; nt++) {
            int col = f0 + wn + nt * 8 + 2 * qc;
#pragma unroll
            for (int h = 0; h < 2; h++) {
                int r = row0 + wr + mt * 16 + qr + h * 8;
                if (r >= cnt) continue;
                float u0 = accU[mt][nt][h * 2 + 0], u1 = accU[mt][nt][h * 2 + 1];
                float g0 = accG[mt][nt][h * 2 + 0], g1 = accG[mt][nt][h * 2 + 1];
                float s0 = u0 / (1.0f + expf(-u0)) * g0;
                float s1 = u1 / (1.0f + expf(-u1)) * g1;
                uint2 o; o.x = f2tf(s0); o.y = f2tf(s1);
                *(uint2*)(g_act + ((size_t)e * T + r) * F + col) = o;
            }
        }
}

// ---------------- kernel 3: tf32 down GEMM + weighted scatter ----------------
// 128 threads, 4 warps (2 row x 2 col), block tile 128x128, warp tile 64x64. 2 CTAs/SM.
__global__ __launch_bounds__(128, 2) void down_kernel(float* __restrict__ y) {
    extern __shared__ uint32_t sm[];
    uint32_t* AsB = sm;                 // [2][BM][36]
    uint32_t* BsB = sm + 2 * AS_WORDS;  // [2][BK][136]

    int e = blockIdx.x / MT;
    int mtile = blockIdx.x % MT;
    int cnt = g_count[e];
    int row0 = mtile * BM;
    if (row0 >= cnt) return;
    int n0 = blockIdx.y * 128;

    const uint32_t* A = g_act + ((size_t)e * T + row0) * F;
    const uint32_t* W = g_wd_tf + (size_t)e * F * H + n0;

    int tid = threadIdx.x;
    uint32_t as_base = smem_u32(AsB);
    uint32_t bs_base = smem_u32(BsB);

    // A: 1024 chunks -> 8/thread. B: 32x128 = 1024 chunks -> 8/thread.
    auto loadA = [&](int buf, int kn) {
        uint32_t dst = as_base + buf * AS_WORDS * 4;
#pragma unroll
        for (int j = 0; j < 8; j++) {
            int c = tid + j * 128;
            int m = c >> 3, seg = c & 7;
            cp16(dst + (m * AS_STRIDE + seg * 4) * 4,
                 A + (size_t)m * F + kn + seg * 4);
        }
    };
    auto loadB = [&](int buf, int kn) {
        uint32_t dst = bs_base + buf * BD_WORDS * 4;
#pragma unroll
        for (int j = 0; j < 8; j++) {
            int c = tid + j * 128;
            int kk = c >> 5, seg = c & 31;
            cp16(dst + (kk * BD_STRIDE + seg * 4) * 4,
                 W + (size_t)(kn + kk) * H + seg * 4);
        }
    };

    loadA(0, 0); loadB(0, 0); CP_COMMIT();
    loadA(1, BK); loadB(1, BK); CP_COMMIT();

    int wid = tid >> 5, lane = tid & 31;
    int wr = (wid >> 1) * 64;     // 0 or 64
    int wn = (wid & 1) * 64;      // 0 or 64
    int qr = lane >> 2, qc = lane & 3;

    float acc[4][8][4];
#pragma unroll
    for (int mt = 0; mt < 4; mt++)
#pragma unroll
        for (int nt = 0; nt < 8; nt++)
#pragma unroll
            for (int i = 0; i < 4; i++) acc[mt][nt][i] = 0.0f;

    const int NIT = F / BK;
    for (int i = 0; i < NIT; i++) {
        int b = i & 1;
        CP_WAIT1();
        __syncthreads();

        const uint32_t* Ab = AsB + b * AS_WORDS;
        const uint32_t* Bb = BsB + b * BD_WORDS;
#pragma unroll
        for (int ks = 0; ks < 4; ks++) {
            int c = ks * 8 + qc;
            uint32_t a[4][4], bfr[8][2];
#pragma unroll
            for (int mt = 0; mt < 4; mt++) {
                const uint32_t* ap = Ab + (wr + mt * 16 + qr) * AS_STRIDE + c;
                a[mt][0] = ap[0];
                a[mt][1] = ap[8 * AS_STRIDE];
                a[mt][2] = ap[4];
                a[mt][3] = ap[8 * AS_STRIDE + 4];
            }
#pragma unroll
            for (int nt = 0; nt < 8; nt++) {
                int n = wn + nt * 8 + qr;
                bfr[nt][0] = Bb[c * BD_STRIDE + n];
                bfr[nt][1] = Bb[(c + 4) * BD_STRIDE + n];
            }
#pragma unroll
            for (int mt = 0; mt < 4; mt++)
#pragma unroll
                for (int nt = 0; nt < 8; nt++)
                    mma8(acc[mt][nt], a[mt], bfr[nt]);
        }
        __syncthreads();
        if (i + 2 < NIT) {
            int kn = (i + 2) * BK;
            loadA(b, kn); loadB(b, kn);
        }
        CP_COMMIT();
    }

    // weighted scatter
#pragma unroll
    for (int mt = 0; mt < 4; mt++)
#pragma unroll
        for (int nt = 0; nt < 8; nt++) {
            int col = n0 + wn + nt * 8 + 2 * qc;
#pragma unroll
            for (int h = 0; h < 2; h++) {
                int r = row0 + wr + mt * 16 + qr + h * 8;
                if (r >= cnt) continue;
                int tok = g_idx[e * T + r];
                float wgt = g_wt[e * T + r];
                float* yr = y + (size_t)tok * H + col;
                atomicAdd(&yr[0], acc[mt][nt][h * 2 + 0] * wgt);
                atomicAdd(&yr[1], acc[mt][nt][h * 2 + 1] * wgt);
            }
        }
}

// ---------------- launch ----------------
extern "C" void kernel_launch(void* const* d_in, const int* in_sizes, int n_in,
                              void* d_out, int out_size) {
    const float* x     = (const float*)d_in[0];
    const float* gw    = (const float*)d_in[1];
    const float* wup   = (const float*)d_in[2];
    const float* wgate = (const float*)d_in[3];
    const float* wdown = (const float*)d_in[4];
    float* y = (float*)d_out;

    int write_logits = (out_size >= T * H + T * NE) ? 1 : 0;
    float* logits = y + (size_t)T * H;

    uint32_t *wu_tf, *wg_tf, *wd_tf, *x_tf;
    cudaGetSymbolAddress((void**)&wu_tf, g_wu_tf);
    cudaGetSymbolAddress((void**)&wg_tf, g_wg_tf);
    cudaGetSymbolAddress((void**)&wd_tf, g_wd_tf);
    cudaGetSymbolAddress((void**)&x_tf, g_x_tf);

    cudaFuncSetAttribute(upgate_kernel, cudaFuncAttributeMaxDynamicSharedMemorySize, SMEM_UPGATE);
    cudaFuncSetAttribute(down_kernel,   cudaFuncAttributeMaxDynamicSharedMemorySize, SMEM_DOWN);

    zero_kernel<<<256, 256>>>(y);
    int nw = NE * H * F / 4;
    cvt_kernel<<<2048, 256>>>((const float4*)wup,   (uint4*)wu_tf, nw);
    cvt_kernel<<<2048, 256>>>((const float4*)wgate, (uint4*)wg_tf, nw);
    cvt_kernel<<<2048, 256>>>((const float4*)wdown, (uint4*)wd_tf, nw);
    cvt_kernel<<<512, 256>>>((const float4*)x, (uint4*)x_tf, T * H / 4);
    router_kernel<<<T / 4, 128>>>(x, gw, logits, write_logits);
    upgate_kernel<<<dim3(NE * MT, F / 64), 128, SMEM_UPGATE>>>();
    down_kernel<<<dim3(NE * MT, H / 128), 128, SMEM_DOWN>>>(y);
}

// round 10
// speedup vs baseline: 8.8788x; 1.6605x over previous
#include <cuda_runtime.h>
#include <cuda_fp16.h>
#include <math.h>
#include <stdint.h>

#define NE 8
#define H 1024
#define F 3584
#define T 4096

#define BM 128
#define BK 64              // halves of K per mainloop iter (4 k16 slices)
#define MT (T / BM)

// smem strides in 32-bit words (each word = 2 halves)
#define ASTR 36            // 32 data words + 4 pad
#define A_WORDS (BM * ASTR)          // 4608
#define BUSTR 36
#define BU_WORDS (BK * BUSTR)        // 2304 (64 k-rows x 36)
#define BDSTR 68           // 64 data words + 4 pad
#define BD_WORDS (BK * BDSTR)        // 4352

#define SMEM_UPG ((2 * A_WORDS + 4 * BU_WORDS) * 4)   // 73728 B
#define SMEM_DWN ((2 * A_WORDS + 2 * BD_WORDS) * 4)   // 71680 B

// ---------------- scratch (device globals) ----------------
__device__ int    g_count[NE];
__device__ int    g_idx[NE * T];
__device__ float  g_wt[NE * T];
__device__ __half g_act[(size_t)NE * T * F];
__device__ __half g_wu_h[(size_t)NE * H * F];
__device__ __half g_wg_h[(size_t)NE * H * F];
__device__ __half g_wd_h[(size_t)NE * F * H];
__device__ __half g_x_h[(size_t)T * H];

// ---------------- helpers ----------------
__device__ __forceinline__ uint32_t smem_u32(const void* p) {
    uint32_t a;
    asm("{ .reg .u64 t; cvta.to.shared.u64 t, %1; cvt.u32.u64 %0, t; }" : "=r"(a) : "l"(p));
    return a;
}
__device__ __forceinline__ void cp16(uint32_t dst, const void* src) {
    asm volatile("cp.async.cg.shared.global [%0], [%1], 16;" :: "r"(dst), "l"(src));
}
#define CP_COMMIT() asm volatile("cp.async.commit_group;" ::: "memory")
#define CP_WAIT1()  asm volatile("cp.async.wait_group 1;" ::: "memory")

__device__ __forceinline__ void ldm_x4(uint32_t* r, uint32_t addr) {
    asm volatile("ldmatrix.sync.aligned.m8n8.x4.shared.b16 {%0,%1,%2,%3}, [%4];"
        : "=r"(r[0]), "=r"(r[1]), "=r"(r[2]), "=r"(r[3]) : "r"(addr));
}
__device__ __forceinline__ void ldm_x4t(uint32_t* r, uint32_t addr) {
    asm volatile("ldmatrix.sync.aligned.m8n8.x4.trans.shared.b16 {%0,%1,%2,%3}, [%4];"
        : "=r"(r[0]), "=r"(r[1]), "=r"(r[2]), "=r"(r[3]) : "r"(addr));
}
__device__ __forceinline__ void mma16(float* d, const uint32_t* a, const uint32_t* b) {
    asm volatile(
        "mma.sync.aligned.m16n8k16.row.col.f32.f16.f16.f32 "
        "{%0,%1,%2,%3},{%4,%5,%6,%7},{%8,%9},{%0,%1,%2,%3};"
        : "+f"(d[0]), "+f"(d[1]), "+f"(d[2]), "+f"(d[3])
        : "r"(a[0]), "r"(a[1]), "r"(a[2]), "r"(a[3]), "r"(b[0]), "r"(b[1]));
}

// ---------------- kernel 0: zero y + counters ----------------
__global__ void zero_kernel(float* __restrict__ y) {
    size_t n = (size_t)T * H;
    size_t stride = (size_t)gridDim.x * blockDim.x;
    for (size_t i = (size_t)blockIdx.x * blockDim.x + threadIdx.x; i < n; i += stride)
        y[i] = 0.0f;
    if (blockIdx.x == 0 && threadIdx.x < NE) g_count[threadIdx.x] = 0;
}

// ---------------- kernel: fp32 -> fp16 pre-convert ----------------
__global__ void cvth_kernel(const float4* __restrict__ src, uint2* __restrict__ dst, int n4) {
    int stride = gridDim.x * blockDim.x;
    for (int i = blockIdx.x * blockDim.x + threadIdx.x; i < n4; i += stride) {
        float4 v = src[i];
        __half2 h0 = __floats2half2_rn(v.x, v.y);
        __half2 h1 = __floats2half2_rn(v.z, v.w);
        uint2 o;
        o.x = *(uint32_t*)&h0;
        o.y = *(uint32_t*)&h1;
        dst[i] = o;
    }
}

// ---------------- kernel 1: router (fp32) ----------------
__global__ void router_kernel(const float* __restrict__ x,
                              const float* __restrict__ gw,
                              float* __restrict__ logits_out,
                              int write_logits) {
    int warp = threadIdx.x >> 5;
    int lane = threadIdx.x & 31;
    int t = blockIdx.x * 4 + warp;
    if (t >= T) return;
    const float* xr = x + (size_t)t * H;

    float acc[NE];
#pragma unroll
    for (int e = 0; e < NE; e++) acc[e] = 0.0f;
    for (int k = lane; k < H; k += 32) {
        float xv = xr[k];
        const float* g = gw + (size_t)k * NE;
#pragma unroll
        for (int e = 0; e < NE; e++) acc[e] += xv * g[e];
    }
#pragma unroll
    for (int off = 16; off > 0; off >>= 1)
#pragma unroll
        for (int e = 0; e < NE; e++)
            acc[e] += __shfl_down_sync(0xffffffffu, acc[e], off);

    if (lane == 0) {
        if (write_logits) {
#pragma unroll
            for (int e = 0; e < NE; e++) logits_out[(size_t)t * NE + e] = acc[e];
        }
        int i1 = 0;
#pragma unroll
        for (int e = 1; e < NE; e++) if (acc[e] > acc[i1]) i1 = e;
        int i2 = (i1 == 0) ? 1 : 0;
#pragma unroll
        for (int e = 0; e < NE; e++)
            if (e != i1 && acc[e] > acc[i2]) i2 = e;
        float w1 = 1.0f / (1.0f + expf(acc[i2] - acc[i1]));
        float w2 = 1.0f / (1.0f + expf(acc[i1] - acc[i2]));
        int p1 = atomicAdd(&g_count[i1], 1);
        g_idx[i1 * T + p1] = t; g_wt[i1 * T + p1] = w1;
        int p2 = atomicAdd(&g_count[i2], 1);
        g_idx[i2 * T + p2] = t; g_wt[i2 * T + p2] = w2;
    }
}

// ---------------- kernel 2: fp16 up+gate GEMM + SiLU ----------------
// 128 threads, 4 warps (2x2), block tile 128x64 per matrix, warp tile 64x32 per matrix.
// BK=64 halves per iter, cp.async double buffer, ldmatrix frags. 2 CTAs/SM.
__global__ __launch_bounds__(128, 2) void upgate_kernel() {
    extern __shared__ uint32_t sm[];
    uint32_t* AsB = sm;                              // [2][128][36]
    uint32_t* BuB = sm + 2 * A_WORDS;                // [2][64][36]
    uint32_t* BgB = BuB + 2 * BU_WORDS;              // [2][64][36]
    __shared__ int toks[BM];

    int e = blockIdx.x / MT;
    int mtile = blockIdx.x % MT;
    int cnt = g_count[e];
    int row0 = mtile * BM;
    if (row0 >= cnt) return;
    int f0 = blockIdx.y * 64;

    int tid = threadIdx.x;
    if (tid < BM) {
        int r = row0 + tid;
        toks[tid] = (r < cnt) ? g_idx[e * T + r] : g_idx[e * T];
    }
    __syncthreads();

    const __half* Wu = g_wu_h + (size_t)e * H * F + f0;
    const __half* Wg = g_wg_h + (size_t)e * H * F + f0;

    uint32_t as_base = smem_u32(AsB);
    uint32_t bu_base = smem_u32(BuB);
    uint32_t bg_base = smem_u32(BgB);

    // A: 128 rows x 8 chunks(16B=8 halves) = 1024 -> 8/thread
    auto loadA = [&](int buf, int kn) {
        uint32_t dst = as_base + buf * A_WORDS * 4;
#pragma unroll
        for (int j = 0; j < 8; j++) {
            int c = tid + j * 128;
            int m = c >> 3, seg = c & 7;
            cp16(dst + (m * ASTR + seg * 4) * 4,
                 g_x_h + (size_t)toks[m] * H + kn + seg * 8);
        }
    };
    // B: 64 k-rows x 8 chunks = 512 per mat -> 4/thread each
    auto loadB = [&](int buf, int kn) {
        uint32_t du = bu_base + buf * BU_WORDS * 4;
        uint32_t dg = bg_base + buf * BU_WORDS * 4;
#pragma unroll
        for (int j = 0; j < 4; j++) {
            int c = tid + j * 128;
            int kk = c >> 3, seg = c & 7;
            uint32_t off = (kk * BUSTR + seg * 4) * 4;
            size_t gi = (size_t)(kn + kk) * F + seg * 8;
            cp16(du + off, Wu + gi);
            cp16(dg + off, Wg + gi);
        }
    };

    loadA(0, 0); loadB(0, 0); CP_COMMIT();
    loadA(1, BK); loadB(1, BK); CP_COMMIT();

    int wid = tid >> 5, lane = tid & 31;
    int wr = (wid >> 1) * 64;     // warp rows: 0 or 64
    int wn = (wid & 1) * 32;      // warp cols within 64: 0 or 32
    int qr = lane >> 2, qc = lane & 3;

    // ldmatrix per-lane address components
    int lRow = lane & 15;                  // row within 16
    int lHi  = (lane & 16) ? 4 : 0;        // word offset for k8..15 (A) / n8..15 (B)
    uint32_t aLane = ((wr + lRow) * ASTR + lHi) * 4;               // + mt*16*ASTR*4 + ks*8*4
    uint32_t bLaneU = (lRow * BUSTR + (wn >> 1) + lHi) * 4;        // + ks*16*BUSTR*4 + ntp*8*4

    float accU[4][4][4], accG[4][4][4];
#pragma unroll
    for (int mt = 0; mt < 4; mt++)
#pragma unroll
        for (int nt = 0; nt < 4; nt++)
#pragma unroll
            for (int i = 0; i < 4; i++) { accU[mt][nt][i] = 0.0f; accG[mt][nt][i] = 0.0f; }

    const int NIT = H / BK;   // 16
    for (int i = 0; i < NIT; i++) {
        int b = i & 1;
        CP_WAIT1();
        __syncthreads();

        uint32_t aB = as_base + b * A_WORDS * 4 + aLane;
        uint32_t uB = bu_base + b * BU_WORDS * 4 + bLaneU;
        uint32_t gB = bg_base + b * BU_WORDS * 4 + bLaneU;
#pragma unroll
        for (int ks = 0; ks < 4; ks++) {
            uint32_t a[4][4];
#pragma unroll
            for (int mt = 0; mt < 4; mt++)
                ldm_x4(a[mt], aB + (mt * 16 * ASTR + ks * 8) * 4);
            uint32_t bu[2][4], bg[2][4];
#pragma unroll
            for (int ntp = 0; ntp < 2; ntp++) {
                uint32_t koff = (ks * 16 * BUSTR + ntp * 8) * 4;
                ldm_x4t(bu[ntp], uB + koff);
                ldm_x4t(bg[ntp], gB + koff);
            }
#pragma unroll
            for (int mt = 0; mt < 4; mt++)
#pragma unroll
                for (int ntp = 0; ntp < 2; ntp++) {
                    mma16(accU[mt][ntp * 2 + 0], a[mt], &bu[ntp][0]);
                    mma16(accU[mt][ntp * 2 + 1], a[mt], &bu[ntp][2]);
                    mma16(accG[mt][ntp * 2 + 0], a[mt], &bg[ntp][0]);
                    mma16(accG[mt][ntp * 2 + 1], a[mt], &bg[ntp][2]);
                }
        }
        __syncthreads();
        if (i + 2 < NIT) {
            int kn = (i + 2) * BK;
            loadA(b, kn); loadB(b, kn);
        }
        CP_COMMIT();
    }

    // epilogue: silu(up)*gate -> g_act (fp16)
#pragma unroll
    for (int mt = 0; mt < 4; mt++)
#pragma unroll
        for (int nt = 0; nt < 4; nt++) {
            int col = f0 + wn + nt * 8 + 2 * qc;
#pragma unroll
            for (int h = 0; h < 2; h++) {
                int r = row0 + wr + mt * 16 + qr + h * 8;
                if (r >= cnt) continue;
                float u0 = accU[mt][nt][h * 2 + 0], u1 = accU[mt][nt][h * 2 + 1];
                float g0 = accG[mt][nt][h * 2 + 0], g1 = accG[mt][nt][h * 2 + 1];
                float s0 = u0 / (1.0f + expf(-u0)) * g0;
                float s1 = u1 / (1.0f + expf(-u1)) * g1;
                *(__half2*)(g_act + ((size_t)e * T + r) * F + col) = __floats2half2_rn(s0, s1);
            }
        }
}

// ---------------- kernel 3: fp16 down GEMM + weighted scatter ----------------
// 128 threads, 4 warps (2x2), block tile 128x128, warp tile 64x64. 2 CTAs/SM.
__global__ __launch_bounds__(128, 2) void down_kernel(float* __restrict__ y) {
    extern __shared__ uint32_t sm[];
    uint32_t* AsB = sm;                 // [2][128][36]
    uint32_t* BsB = sm + 2 * A_WORDS;   // [2][64][68]

    int e = blockIdx.x / MT;
    int mtile = blockIdx.x % MT;
    int cnt = g_count[e];
    int row0 = mtile * BM;
    if (row0 >= cnt) return;
    int n0 = blockIdx.y * 128;

    const __half* A = g_act + ((size_t)e * T + row0) * F;
    const __half* W = g_wd_h + (size_t)e * F * H + n0;

    int tid = threadIdx.x;
    uint32_t as_base = smem_u32(AsB);
    uint32_t bs_base = smem_u32(BsB);

    auto loadA = [&](int buf, int kn) {
        uint32_t dst = as_base + buf * A_WORDS * 4;
#pragma unroll
        for (int j = 0; j < 8; j++) {
            int c = tid + j * 128;
            int m = c >> 3, seg = c & 7;
            cp16(dst + (m * ASTR + seg * 4) * 4,
                 A + (size_t)m * F + kn + seg * 8);
        }
    };
    // B: 64 k-rows x 16 chunks = 1024 -> 8/thread
    auto loadB = [&](int buf, int kn) {
        uint32_t dst = bs_base + buf * BD_WORDS * 4;
#pragma unroll
        for (int j = 0; j < 8; j++) {
            int c = tid + j * 128;
            int kk = c >> 4, seg = c & 15;
            cp16(dst + (kk * BDSTR + seg * 4) * 4,
                 W + (size_t)(kn + kk) * H + seg * 8);
        }
    };

    loadA(0, 0); loadB(0, 0); CP_COMMIT();
    loadA(1, BK); loadB(1, BK); CP_COMMIT();

    int wid = tid >> 5, lane = tid & 31;
    int wr = (wid >> 1) * 64;     // 0 or 64
    int wn = (wid & 1) * 64;      // 0 or 64
    int qr = lane >> 2, qc = lane & 3;

    int lRow = lane & 15;
    int lHi  = (lane & 16) ? 4 : 0;
    uint32_t aLane = ((wr + lRow) * ASTR + lHi) * 4;
    uint32_t bLane = (lRow * BDSTR + (wn >> 1) + lHi) * 4;

    float acc[4][8][4];
#pragma unroll
    for (int mt = 0; mt < 4; mt++)
#pragma unroll
        for (int nt = 0; nt < 8; nt++)
#pragma unroll
            for (int i = 0; i < 4; i++) acc[mt][nt][i] = 0.0f;

    const int NIT = F / BK;   // 56
    for (int i = 0; i < NIT; i++) {
        int b = i & 1;
        CP_WAIT1();
        __syncthreads();

        uint32_t aB = as_base + b * A_WORDS * 4 + aLane;
        uint32_t bB = bs_base + b * BD_WORDS * 4 + bLane;
#pragma unroll
        for (int ks = 0; ks < 4; ks++) {
            uint32_t a[4][4];
#pragma unroll
            for (int mt = 0; mt < 4; mt++)
                ldm_x4(a[mt], aB + (mt * 16 * ASTR + ks * 8) * 4);
            uint32_t bfr[4][4];
#pragma unroll
            for (int ntp = 0; ntp < 4; ntp++)
                ldm_x4t(bfr[ntp], bB + (ks * 16 * BDSTR + ntp * 8) * 4);
#pragma unroll
            for (int mt = 0; mt < 4; mt++)
#pragma unroll
                for (int ntp = 0; ntp < 4; ntp++) {
                    mma16(acc[mt][ntp * 2 + 0], a[mt], &bfr[ntp][0]);
                    mma16(acc[mt][ntp * 2 + 1], a[mt], &bfr[ntp][2]);
                }
        }
        __syncthreads();
        if (i + 2 < NIT) {
            int kn = (i + 2) * BK;
            loadA(b, kn); loadB(b, kn);
        }
        CP_COMMIT();
    }

    // weighted scatter
#pragma unroll
    for (int mt = 0; mt < 4; mt++)
#pragma unroll
        for (int nt = 0; nt < 8; nt++) {
            int col = n0 + wn + nt * 8 + 2 * qc;
#pragma unroll
            for (int h = 0; h < 2; h++) {
                int r = row0 + wr + mt * 16 + qr + h * 8;
                if (r >= cnt) continue;
                int tok = g_idx[e * T + r];
                float wgt = g_wt[e * T + r];
                float* yr = y + (size_t)tok * H + col;
                atomicAdd(&yr[0], acc[mt][nt][h * 2 + 0] * wgt);
                atomicAdd(&yr[1], acc[mt][nt][h * 2 + 1] * wgt);
            }
        }
}

// ---------------- launch ----------------
extern "C" void kernel_launch(void* const* d_in, const int* in_sizes, int n_in,
                              void* d_out, int out_size) {
    const float* x     = (const float*)d_in[0];
    const float* gw    = (const float*)d_in[1];
    const float* wup   = (const float*)d_in[2];
    const float* wgate = (const float*)d_in[3];
    const float* wdown = (const float*)d_in[4];
    float* y = (float*)d_out;

    int write_logits = (out_size >= T * H + T * NE) ? 1 : 0;
    float* logits = y + (size_t)T * H;

    __half *wu_h, *wg_h, *wd_h, *x_h;
    cudaGetSymbolAddress((void**)&wu_h, g_wu_h);
    cudaGetSymbolAddress((void**)&wg_h, g_wg_h);
    cudaGetSymbolAddress((void**)&wd_h, g_wd_h);
    cudaGetSymbolAddress((void**)&x_h, g_x_h);

    cudaFuncSetAttribute(upgate_kernel, cudaFuncAttributeMaxDynamicSharedMemorySize, SMEM_UPG);
    cudaFuncSetAttribute(down_kernel,   cudaFuncAttributeMaxDynamicSharedMemorySize, SMEM_DWN);

    zero_kernel<<<256, 256>>>(y);
    int nw = NE * H * F / 4;
    cvth_kernel<<<2048, 256>>>((const float4*)wup,   (uint2*)wu_h, nw);
    cvth_kernel<<<2048, 256>>>((const float4*)wgate, (uint2*)wg_h, nw);
    cvth_kernel<<<2048, 256>>>((const float4*)wdown, (uint2*)wd_h, nw);
    cvth_kernel<<<512, 256>>>((const float4*)x, (uint2*)x_h, T * H / 4);
    router_kernel<<<T / 4, 128>>>(x, gw, logits, write_logits);
    upgate_kernel<<<dim3(NE * MT, F / 64), 128, SMEM_UPG>>>();
    down_kernel<<<dim3(NE * MT, H / 128), 128, SMEM_DWN>>>(y);
}

// round 12
// speedup vs baseline: 9.5311x; 1.0735x over previous
#include <cuda_runtime.h>
#include <cuda_fp16.h>
#include <math.h>
#include <stdint.h>

#define NE 8
#define H 1024
#define F 3584
#define T 4096

#define BM 128
#define BK 64              // halves of K per mainloop iter (4 k16 slices)
#define MT (T / BM)

// smem strides in 32-bit words (each word = 2 halves)
#define ASTR 36
#define A_WORDS (BM * ASTR)          // 4608
#define BUSTR 36
#define BU_WORDS (BK * BUSTR)        // 2304
#define BDSTR 68
#define BD_WORDS (BK * BDSTR)        // 4352

// 3-stage pipelines
#define UPG_STAGE (A_WORDS + 2 * BU_WORDS)          // 9216 words
#define DWN_STAGE (A_WORDS + BD_WORDS)              // 8960 words
#define SMEM_UPG (3 * UPG_STAGE * 4)                // 110592 B
#define SMEM_DWN (3 * DWN_STAGE * 4)                // 107520 B

// ---------------- scratch (device globals) ----------------
__device__ int    g_count[NE];
__device__ int    g_idx[NE * T];
__device__ float  g_wt[NE * T];
__device__ __half g_act[(size_t)NE * T * F];
__device__ __half g_wu_h[(size_t)NE * H * F];
__device__ __half g_wg_h[(size_t)NE * H * F];
__device__ __half g_wd_h[(size_t)NE * F * H];
__device__ __half g_x_h[(size_t)T * H];

// ---------------- helpers ----------------
__device__ __forceinline__ uint32_t smem_u32(const void* p) {
    uint32_t a;
    asm("{ .reg .u64 t; cvta.to.shared.u64 t, %1; cvt.u32.u64 %0, t; }" : "=r"(a) : "l"(p));
    return a;
}
__device__ __forceinline__ void cp16(uint32_t dst, const void* src) {
    asm volatile("cp.async.cg.shared.global [%0], [%1], 16;" :: "r"(dst), "l"(src));
}
#define CP_COMMIT() asm volatile("cp.async.commit_group;" ::: "memory")
#define CP_WAIT1()  asm volatile("cp.async.wait_group 1;" ::: "memory")

__device__ __forceinline__ void ldm_x4(uint32_t* r, uint32_t addr) {
    asm volatile("ldmatrix.sync.aligned.m8n8.x4.shared.b16 {%0,%1,%2,%3}, [%4];"
        : "=r"(r[0]), "=r"(r[1]), "=r"(r[2]), "=r"(r[3]) : "r"(addr));
}
__device__ __forceinline__ void ldm_x4t(uint32_t* r, uint32_t addr) {
    asm volatile("ldmatrix.sync.aligned.m8n8.x4.trans.shared.b16 {%0,%1,%2,%3}, [%4];"
        : "=r"(r[0]), "=r"(r[1]), "=r"(r[2]), "=r"(r[3]) : "r"(addr));
}
__device__ __forceinline__ void mma16(float* d, const uint32_t* a, const uint32_t* b) {
    asm volatile(
        "mma.sync.aligned.m16n8k16.row.col.f32.f16.f16.f32 "
        "{%0,%1,%2,%3},{%4,%5,%6,%7},{%8,%9},{%0,%1,%2,%3};"
        : "+f"(d[0]), "+f"(d[1]), "+f"(d[2]), "+f"(d[3])
        : "r"(a[0]), "r"(a[1]), "r"(a[2]), "r"(a[3]), "r"(b[0]), "r"(b[1]));
}

// ---------------- kernel 0: zero y + counters ----------------
__global__ void zero_kernel(float* __restrict__ y) {
    size_t n = (size_t)T * H;
    size_t stride = (size_t)gridDim.x * blockDim.x;
    for (size_t i = (size_t)blockIdx.x * blockDim.x + threadIdx.x; i < n; i += stride)
        y[i] = 0.0f;
    if (blockIdx.x == 0 && threadIdx.x < NE) g_count[threadIdx.x] = 0;
}

// ---------------- kernel: fp32 -> fp16 pre-convert ----------------
__global__ void cvth_kernel(const float4* __restrict__ src, uint2* __restrict__ dst, int n4) {
    int stride = gridDim.x * blockDim.x;
    for (int i = blockIdx.x * blockDim.x + threadIdx.x; i < n4; i += stride) {
        float4 v = src[i];
        __half2 h0 = __floats2half2_rn(v.x, v.y);
        __half2 h1 = __floats2half2_rn(v.z, v.w);
        uint2 o;
        o.x = *(uint32_t*)&h0;
        o.y = *(uint32_t*)&h1;
        dst[i] = o;
    }
}

// ---------------- kernel 1: router (fp32) ----------------
__global__ void router_kernel(const float* __restrict__ x,
                              const float* __restrict__ gw,
                              float* __restrict__ logits_out,
                              int write_logits) {
    int warp = threadIdx.x >> 5;
    int lane = threadIdx.x & 31;
    int t = blockIdx.x * 4 + warp;
    if (t >= T) return;
    const float* xr = x + (size_t)t * H;

    float acc[NE];
#pragma unroll
    for (int e = 0; e < NE; e++) acc[e] = 0.0f;
    for (int k = lane; k < H; k += 32) {
        float xv = xr[k];
        const float* g = gw + (size_t)k * NE;
#pragma unroll
        for (int e = 0; e < NE; e++) acc[e] += xv * g[e];
    }
#pragma unroll
    for (int off = 16; off > 0; off >>= 1)
#pragma unroll
        for (int e = 0; e < NE; e++)
            acc[e] += __shfl_down_sync(0xffffffffu, acc[e], off);

    if (lane == 0) {
        if (write_logits) {
#pragma unroll
            for (int e = 0; e < NE; e++) logits_out[(size_t)t * NE + e] = acc[e];
        }
        int i1 = 0;
#pragma unroll
        for (int e = 1; e < NE; e++) if (acc[e] > acc[i1]) i1 = e;
        int i2 = (i1 == 0) ? 1 : 0;
#pragma unroll
        for (int e = 0; e < NE; e++)
            if (e != i1 && acc[e] > acc[i2]) i2 = e;
        float w1 = 1.0f / (1.0f + expf(acc[i2] - acc[i1]));
        float w2 = 1.0f / (1.0f + expf(acc[i1] - acc[i2]));
        int p1 = atomicAdd(&g_count[i1], 1);
        g_idx[i1 * T + p1] = t; g_wt[i1 * T + p1] = w1;
        int p2 = atomicAdd(&g_count[i2], 1);
        g_idx[i2 * T + p2] = t; g_wt[i2 * T + p2] = w2;
    }
}

// ---------------- kernel 2: fp16 up+gate GEMM + SiLU ----------------
// 128 threads, 4 warps (2x2), block tile 128x64 per matrix, warp tile 64x32 per matrix.
// 3-stage cp.async pipeline, 1 barrier/iter, ldmatrix frags. 2 CTAs/SM.
__global__ __launch_bounds__(128, 2) void upgate_kernel() {
    extern __shared__ uint32_t sm[];
    // stage s: [A | BU | BG] at sm + s*UPG_STAGE
    __shared__ int toks[BM];

    int e = blockIdx.x / MT;
    int mtile = blockIdx.x % MT;
    int cnt = g_count[e];
    int row0 = mtile * BM;
    if (row0 >= cnt) return;
    int f0 = blockIdx.y * 64;

    int tid = threadIdx.x;
    if (tid < BM) {
        int r = row0 + tid;
        toks[tid] = (r < cnt) ? g_idx[e * T + r] : g_idx[e * T];
    }
    __syncthreads();

    const __half* Wu = g_wu_h + (size_t)e * H * F + f0;
    const __half* Wg = g_wg_h + (size_t)e * H * F + f0;

    uint32_t base = smem_u32(sm);

    auto loadStage = [&](int s, int kn) {
        uint32_t ad = base + (s * UPG_STAGE) * 4;
        uint32_t ud = ad + A_WORDS * 4;
        uint32_t gd = ud + BU_WORDS * 4;
#pragma unroll
        for (int j = 0; j < 8; j++) {
            int c = tid + j * 128;
            int m = c >> 3, seg = c & 7;
            cp16(ad + (m * ASTR + seg * 4) * 4,
                 g_x_h + (size_t)toks[m] * H + kn + seg * 8);
        }
#pragma unroll
        for (int j = 0; j < 4; j++) {
            int c = tid + j * 128;
            int kk = c >> 3, seg = c & 7;
            uint32_t off = (kk * BUSTR + seg * 4) * 4;
            size_t gi = (size_t)(kn + kk) * F + seg * 8;
            cp16(ud + off, Wu + gi);
            cp16(gd + off, Wg + gi);
        }
    };

    loadStage(0, 0); CP_COMMIT();
    loadStage(1, BK); CP_COMMIT();

    int wid = tid >> 5, lane = tid & 31;
    int wr = (wid >> 1) * 64;
    int wn = (wid & 1) * 32;
    int qr = lane >> 2, qc = lane & 3;

    int lRow = lane & 15;
    int lHi  = (lane & 16) ? 4 : 0;
    uint32_t aLane = ((wr + lRow) * ASTR + lHi) * 4;
    uint32_t bLane = (lRow * BUSTR + (wn >> 1) + lHi) * 4;

    float accU[4][4][4], accG[4][4][4];
#pragma unroll
    for (int mt = 0; mt < 4; mt++)
#pragma unroll
        for (int nt = 0; nt < 4; nt++)
#pragma unroll
            for (int i = 0; i < 4; i++) { accU[mt][nt][i] = 0.0f; accG[mt][nt][i] = 0.0f; }

    const int NIT = H / BK;   // 16
    int s = 0;
    for (int i = 0; i < NIT; i++) {
        CP_WAIT1();
        __syncthreads();   // stage s ready; all warps done with stage (s+2)%3

        uint32_t aB = base + (s * UPG_STAGE) * 4 + aLane;
        uint32_t uB = base + (s * UPG_STAGE + A_WORDS) * 4 + bLane;
        uint32_t gB = base + (s * UPG_STAGE + A_WORDS + BU_WORDS) * 4 + bLane;
#pragma unroll
        for (int ks = 0; ks < 4; ks++) {
            uint32_t a[4][4];
#pragma unroll
            for (int mt = 0; mt < 4; mt++)
                ldm_x4(a[mt], aB + (mt * 16 * ASTR + ks * 8) * 4);
            uint32_t bu[2][4], bg[2][4];
#pragma unroll
            for (int ntp = 0; ntp < 2; ntp++) {
                uint32_t koff = (ks * 16 * BUSTR + ntp * 8) * 4;
                ldm_x4t(bu[ntp], uB + koff);
                ldm_x4t(bg[ntp], gB + koff);
            }
#pragma unroll
            for (int mt = 0; mt < 4; mt++)
#pragma unroll
                for (int ntp = 0; ntp < 2; ntp++) {
                    mma16(accU[mt][ntp * 2 + 0], a[mt], &bu[ntp][0]);
                    mma16(accU[mt][ntp * 2 + 1], a[mt], &bu[ntp][2]);
                    mma16(accG[mt][ntp * 2 + 0], a[mt], &bg[ntp][0]);
                    mma16(accG[mt][ntp * 2 + 1], a[mt], &bg[ntp][2]);
                }
        }
        if (i + 2 < NIT) {
            int sn = (s + 2) % 3;
            loadStage(sn, (i + 2) * BK);
        }
        CP_COMMIT();
        s = (s + 1) % 3;
    }

    // epilogue: silu(up)*gate -> g_act (fp16)
#pragma unroll
    for (int mt = 0; mt < 4; mt++)
#pragma unroll
        for (int nt = 0; nt < 4; nt++) {
            int col = f0 + wn + nt * 8 + 2 * qc;
#pragma unroll
            for (int h = 0; h < 2; h++) {
                int r = row0 + wr + mt * 16 + qr + h * 8;
                if (r >= cnt) continue;
                float u0 = accU[mt][nt][h * 2 + 0], u1 = accU[mt][nt][h * 2 + 1];
                float g0 = accG[mt][nt][h * 2 + 0], g1 = accG[mt][nt][h * 2 + 1];
                float s0 = u0 / (1.0f + expf(-u0)) * g0;
                float s1 = u1 / (1.0f + expf(-u1)) * g1;
                *(__half2*)(g_act + ((size_t)e * T + r) * F + col) = __floats2half2_rn(s0, s1);
            }
        }
}

// ---------------- kernel 3: fp16 down GEMM + weighted scatter ----------------
// 128 threads, 4 warps (2x2), block tile 128x128, warp tile 64x64.
// 3-stage cp.async pipeline, 1 barrier/iter. 2 CTAs/SM.
__global__ __launch_bounds__(128, 2) void down_kernel(float* __restrict__ y) {
    extern __shared__ uint32_t sm[];
    // stage s: [A | B] at sm + s*DWN_STAGE

    int e = blockIdx.x / MT;
    int mtile = blockIdx.x % MT;
    int cnt = g_count[e];
    int row0 = mtile * BM;
    if (row0 >= cnt) return;
    int n0 = blockIdx.y * 128;

    const __half* A = g_act + ((size_t)e * T + row0) * F;
    const __half* W = g_wd_h + (size_t)e * F * H + n0;

    int tid = threadIdx.x;
    uint32_t base = smem_u32(sm);

    auto loadStage = [&](int s, int kn) {
        uint32_t ad = base + (s * DWN_STAGE) * 4;
        uint32_t bd = ad + A_WORDS * 4;
#pragma unroll
        for (int j = 0; j < 8; j++) {
            int c = tid + j * 128;
            int m = c >> 3, seg = c & 7;
            cp16(ad + (m * ASTR + seg * 4) * 4,
                 A + (size_t)m * F + kn + seg * 8);
        }
#pragma unroll
        for (int j = 0; j < 8; j++) {
            int c = tid + j * 128;
            int kk = c >> 4, seg = c & 15;
            cp16(bd + (kk * BDSTR + seg * 4) * 4,
                 W + (size_t)(kn + kk) * H + seg * 8);
        }
    };

    loadStage(0, 0); CP_COMMIT();
    loadStage(1, BK); CP_COMMIT();

    int wid = tid >> 5, lane = tid & 31;
    int wr = (wid >> 1) * 64;
    int wn = (wid & 1) * 64;
    int qr = lane >> 2, qc = lane & 3;

    int lRow = lane & 15;
    int lHi  = (lane & 16) ? 4 : 0;
    uint32_t aLane = ((wr + lRow) * ASTR + lHi) * 4;
    uint32_t bLane = (lRow * BDSTR + (wn >> 1) + lHi) * 4;

    float acc[4][8][4];
#pragma unroll
    for (int mt = 0; mt < 4; mt++)
#pragma unroll
        for (int nt = 0; nt < 8; nt++)
#pragma unroll
            for (int i = 0; i < 4; i++) acc[mt][nt][i] = 0.0f;

    const int NIT = F / BK;   // 56
    int s = 0;
    for (int i = 0; i < NIT; i++) {
        CP_WAIT1();
        __syncthreads();

        uint32_t aB = base + (s * DWN_STAGE) * 4 + aLane;
        uint32_t bB = base + (s * DWN_STAGE + A_WORDS) * 4 + bLane;
#pragma unroll
        for (int ks = 0; ks < 4; ks++) {
            uint32_t a[4][4];
#pragma unroll
            for (int mt = 0; mt < 4; mt++)
                ldm_x4(a[mt], aB + (mt * 16 * ASTR + ks * 8) * 4);
            uint32_t bfr[4][4];
#pragma unroll
            for (int ntp = 0; ntp < 4; ntp++)
                ldm_x4t(bfr[ntp], bB + (ks * 16 * BDSTR + ntp * 8) * 4);
#pragma unroll
            for (int mt = 0; mt < 4; mt++)
#pragma unroll
                for (int ntp = 0; ntp < 4; ntp++) {
                    mma16(acc[mt][ntp * 2 + 0], a[mt], &bfr[ntp][0]);
                    mma16(acc[mt][ntp * 2 + 1], a[mt], &bfr[ntp][2]);
                }
        }
        if (i + 2 < NIT) {
            int sn = (s + 2) % 3;
            loadStage(sn, (i + 2) * BK);
        }
        CP_COMMIT();
        s = (s + 1) % 3;
    }

    // weighted scatter
#pragma unroll
    for (int mt = 0; mt < 4; mt++)
#pragma unroll
        for (int nt = 0; nt < 8; nt++) {
            int col = n0 + wn + nt * 8 + 2 * qc;
#pragma unroll
            for (int h = 0; h < 2; h++) {
                int r = row0 + wr + mt * 16 + qr + h * 8;
                if (r >= cnt) continue;
                int tok = g_idx[e * T + r];
                float wgt = g_wt[e * T + r];
                float* yr = y + (size_t)tok * H + col;
                atomicAdd(&yr[0], acc[mt][nt][h * 2 + 0] * wgt);
                atomicAdd(&yr[1], acc[mt][nt][h * 2 + 1] * wgt);
            }
        }
}

// ---------------- launch ----------------
extern "C" void kernel_launch(void* const* d_in, const int* in_sizes, int n_in,
                              void* d_out, int out_size) {
    const float* x     = (const float*)d_in[0];
    const float* gw    = (const float*)d_in[1];
    const float* wup   = (const float*)d_in[2];
    const float* wgate = (const float*)d_in[3];
    const float* wdown = (const float*)d_in[4];
    float* y = (float*)d_out;

    int write_logits = (out_size >= T * H + T * NE) ? 1 : 0;
    float* logits = y + (size_t)T * H;

    __half *wu_h, *wg_h, *wd_h, *x_h;
    cudaGetSymbolAddress((void**)&wu_h, g_wu_h);
    cudaGetSymbolAddress((void**)&wg_h, g_wg_h);
    cudaGetSymbolAddress((void**)&wd_h, g_wd_h);
    cudaGetSymbolAddress((void**)&x_h, g_x_h);

    cudaFuncSetAttribute(upgate_kernel, cudaFuncAttributeMaxDynamicSharedMemorySize, SMEM_UPG);
    cudaFuncSetAttribute(down_kernel,   cudaFuncAttributeMaxDynamicSharedMemorySize, SMEM_DWN);

    zero_kernel<<<256, 256>>>(y);
    int nw = NE * H * F / 4;
    cvth_kernel<<<2048, 256>>>((const float4*)wup,   (uint2*)wu_h, nw);
    cvth_kernel<<<2048, 256>>>((const float4*)wgate, (uint2*)wg_h, nw);
    cvth_kernel<<<2048, 256>>>((const float4*)wdown, (uint2*)wd_h, nw);
    cvth_kernel<<<512, 256>>>((const float4*)x, (uint2*)x_h, T * H / 4);
    router_kernel<<<T / 4, 128>>>(x, gw, logits, write_logits);
    upgate_kernel<<<dim3(NE * MT, F / 64), 128, SMEM_UPG>>>();
    down_kernel<<<dim3(NE * MT, H / 128), 128, SMEM_DWN>>>(y);
}

// round 14
// speedup vs baseline: 10.1868x; 1.0688x over previous
#include <cuda_runtime.h>
#include <cuda_fp16.h>
#include <math.h>
#include <stdint.h>

#define NE 8
#define H 1024
#define F 3584
#define T 4096

#define BM 128
#define BK 32              // halves of K per mainloop iter (2 k16 slices)
#define MT (T / BM)

// smem strides in 32-bit words (each word = 2 halves)
#define ASTR 20            // 16 data words + 4 pad (bank-clean for ldmatrix)
#define A_WORDS (BM * ASTR)          // 2560
#define BUSTR 36
#define BU_WORDS (BK * BUSTR)        // 1152
#define BDSTR 68
#define BD_WORDS (BK * BDSTR)        // 2176

// 3-stage pipelines
#define UPG_STAGE (A_WORDS + 2 * BU_WORDS)          // 4864 words (19456 B)
#define DWN_STAGE (A_WORDS + BD_WORDS)              // 4736 words (18944 B)
#define SMEM_UPG (3 * UPG_STAGE * 4)                // 58368 B
#define SMEM_DWN (3 * DWN_STAGE * 4)                // 56832 B

// ---------------- scratch (device globals) ----------------
__device__ int    g_count[NE];
__device__ int    g_idx[NE * T];
__device__ float  g_wt[NE * T];
__device__ __half g_act[(size_t)NE * T * F];
__device__ __half g_wu_h[(size_t)NE * H * F];
__device__ __half g_wg_h[(size_t)NE * H * F];
__device__ __half g_wd_h[(size_t)NE * F * H];
__device__ __half g_x_h[(size_t)T * H];

// ---------------- helpers ----------------
__device__ __forceinline__ uint32_t smem_u32(const void* p) {
    uint32_t a;
    asm("{ .reg .u64 t; cvta.to.shared.u64 t, %1; cvt.u32.u64 %0, t; }" : "=r"(a) : "l"(p));
    return a;
}
__device__ __forceinline__ void cp16(uint32_t dst, const void* src) {
    asm volatile("cp.async.cg.shared.global [%0], [%1], 16;" :: "r"(dst), "l"(src));
}
#define CP_COMMIT() asm volatile("cp.async.commit_group;" ::: "memory")
#define CP_WAIT1()  asm volatile("cp.async.wait_group 1;" ::: "memory")

__device__ __forceinline__ void ldm_x4(uint32_t* r, uint32_t addr) {
    asm volatile("ldmatrix.sync.aligned.m8n8.x4.shared.b16 {%0,%1,%2,%3}, [%4];"
        : "=r"(r[0]), "=r"(r[1]), "=r"(r[2]), "=r"(r[3]) : "r"(addr));
}
__device__ __forceinline__ void ldm_x4t(uint32_t* r, uint32_t addr) {
    asm volatile("ldmatrix.sync.aligned.m8n8.x4.trans.shared.b16 {%0,%1,%2,%3}, [%4];"
        : "=r"(r[0]), "=r"(r[1]), "=r"(r[2]), "=r"(r[3]) : "r"(addr));
}
__device__ __forceinline__ void mma16(float* d, const uint32_t* a, const uint32_t* b) {
    asm volatile(
        "mma.sync.aligned.m16n8k16.row.col.f32.f16.f16.f32 "
        "{%0,%1,%2,%3},{%4,%5,%6,%7},{%8,%9},{%0,%1,%2,%3};"
        : "+f"(d[0]), "+f"(d[1]), "+f"(d[2]), "+f"(d[3])
        : "r"(a[0]), "r"(a[1]), "r"(a[2]), "r"(a[3]), "r"(b[0]), "r"(b[1]));
}

// ---------------- kernel 0: zero y + counters ----------------
__global__ void zero_kernel(float* __restrict__ y) {
    size_t n = (size_t)T * H;
    size_t stride = (size_t)gridDim.x * blockDim.x;
    for (size_t i = (size_t)blockIdx.x * blockDim.x + threadIdx.x; i < n; i += stride)
        y[i] = 0.0f;
    if (blockIdx.x == 0 && threadIdx.x < NE) g_count[threadIdx.x] = 0;
}

// ---------------- kernel: fp32 -> fp16 pre-convert (weights) ----------------
__global__ void cvth_kernel(const float4* __restrict__ src, uint2* __restrict__ dst, int n4) {
    int stride = gridDim.x * blockDim.x;
    for (int i = blockIdx.x * blockDim.x + threadIdx.x; i < n4; i += stride) {
        float4 v = src[i];
        __half2 h0 = __floats2half2_rn(v.x, v.y);
        __half2 h1 = __floats2half2_rn(v.z, v.w);
        uint2 o;
        o.x = *(uint32_t*)&h0;
        o.y = *(uint32_t*)&h1;
        dst[i] = o;
    }
}

// ---------------- kernel 1: router (fp32) + x fp16 convert fused ----------------
__global__ void router_kernel(const float* __restrict__ x,
                              const float* __restrict__ gw,
                              float* __restrict__ logits_out,
                              int write_logits) {
    int warp = threadIdx.x >> 5;
    int lane = threadIdx.x & 31;
    int t = blockIdx.x * 4 + warp;
    if (t >= T) return;
    const float* xr = x + (size_t)t * H;
    __half* xh = g_x_h + (size_t)t * H;

    float acc[NE];
#pragma unroll
    for (int e = 0; e < NE; e++) acc[e] = 0.0f;
    for (int k = lane; k < H; k += 32) {
        float xv = xr[k];
        xh[k] = __float2half_rn(xv);
        const float* g = gw + (size_t)k * NE;
#pragma unroll
        for (int e = 0; e < NE; e++) acc[e] += xv * g[e];
    }
#pragma unroll
    for (int off = 16; off > 0; off >>= 1)
#pragma unroll
        for (int e = 0; e < NE; e++)
            acc[e] += __shfl_down_sync(0xffffffffu, acc[e], off);

    if (lane == 0) {
        if (write_logits) {
#pragma unroll
            for (int e = 0; e < NE; e++) logits_out[(size_t)t * NE + e] = acc[e];
        }
        int i1 = 0;
#pragma unroll
        for (int e = 1; e < NE; e++) if (acc[e] > acc[i1]) i1 = e;
        int i2 = (i1 == 0) ? 1 : 0;
#pragma unroll
        for (int e = 0; e < NE; e++)
            if (e != i1 && acc[e] > acc[i2]) i2 = e;
        float w1 = 1.0f / (1.0f + expf(acc[i2] - acc[i1]));
        float w2 = 1.0f / (1.0f + expf(acc[i1] - acc[i2]));
        int p1 = atomicAdd(&g_count[i1], 1);
        g_idx[i1 * T + p1] = t; g_wt[i1 * T + p1] = w1;
        int p2 = atomicAdd(&g_count[i2], 1);
        g_idx[i2 * T + p2] = t; g_wt[i2 * T + p2] = w2;
    }
}

// ---------------- kernel 2: fp16 up+gate GEMM + SiLU ----------------
// 128 threads, 4 warps (2x2), block tile 128x64 per matrix, warp tile 64x32 per matrix.
// BK=32, 3-stage cp.async pipeline, 3 CTAs/SM (12 warps/SM).
__global__ __launch_bounds__(128, 3) void upgate_kernel() {
    extern __shared__ uint32_t sm[];
    __shared__ int toks[BM];

    int e = blockIdx.x / MT;
    int mtile = blockIdx.x % MT;
    int cnt = g_count[e];
    int row0 = mtile * BM;
    if (row0 >= cnt) return;
    int f0 = blockIdx.y * 64;

    int tid = threadIdx.x;
    if (tid < BM) {
        int r = row0 + tid;
        toks[tid] = (r < cnt) ? g_idx[e * T + r] : g_idx[e * T];
    }
    __syncthreads();

    const __half* Wu = g_wu_h + (size_t)e * H * F + f0;
    const __half* Wg = g_wg_h + (size_t)e * H * F + f0;

    uint32_t base = smem_u32(sm);

    auto loadStage = [&](int s, int kn) {
        uint32_t ad = base + (s * UPG_STAGE) * 4;
        uint32_t ud = ad + A_WORDS * 4;
        uint32_t gd = ud + BU_WORDS * 4;
        // A: 128 rows x 4 chunks (16B = 8 halves) = 512 -> 4/thread
#pragma unroll
        for (int j = 0; j < 4; j++) {
            int c = tid + j * 128;
            int m = c >> 2, seg = c & 3;
            cp16(ad + (m * ASTR + seg * 4) * 4,
                 g_x_h + (size_t)toks[m] * H + kn + seg * 8);
        }
        // B: 32 k-rows x 8 chunks = 256 per mat -> 2/thread each
#pragma unroll
        for (int j = 0; j < 2; j++) {
            int c = tid + j * 128;
            int kk = c >> 3, seg = c & 7;
            uint32_t off = (kk * BUSTR + seg * 4) * 4;
            size_t gi = (size_t)(kn + kk) * F + seg * 8;
            cp16(ud + off, Wu + gi);
            cp16(gd + off, Wg + gi);
        }
    };

    loadStage(0, 0); CP_COMMIT();
    loadStage(1, BK); CP_COMMIT();

    int wid = tid >> 5, lane = tid & 31;
    int wr = (wid >> 1) * 64;
    int wn = (wid & 1) * 32;
    int qr = lane >> 2, qc = lane & 3;

    int lRow = lane & 15;
    int lHi  = (lane & 16) ? 4 : 0;
    uint32_t aLane = ((wr + lRow) * ASTR + lHi) * 4;
    uint32_t bLane = (lRow * BUSTR + (wn >> 1) + lHi) * 4;

    float accU[4][4][4], accG[4][4][4];
#pragma unroll
    for (int mt = 0; mt < 4; mt++)
#pragma unroll
        for (int nt = 0; nt < 4; nt++)
#pragma unroll
            for (int i = 0; i < 4; i++) { accU[mt][nt][i] = 0.0f; accG[mt][nt][i] = 0.0f; }

    const int NIT = H / BK;   // 32
    int s = 0;
    for (int i = 0; i < NIT; i++) {
        CP_WAIT1();
        __syncthreads();

        uint32_t aB = base + (s * UPG_STAGE) * 4 + aLane;
        uint32_t uB = base + (s * UPG_STAGE + A_WORDS) * 4 + bLane;
        uint32_t gB = base + (s * UPG_STAGE + A_WORDS + BU_WORDS) * 4 + bLane;
#pragma unroll
        for (int ks = 0; ks < 2; ks++) {
            uint32_t a[4][4];
#pragma unroll
            for (int mt = 0; mt < 4; mt++)
                ldm_x4(a[mt], aB + (mt * 16 * ASTR + ks * 8) * 4);
            uint32_t bu[2][4], bg[2][4];
#pragma unroll
            for (int ntp = 0; ntp < 2; ntp++) {
                uint32_t koff = (ks * 16 * BUSTR + ntp * 8) * 4;
                ldm_x4t(bu[ntp], uB + koff);
                ldm_x4t(bg[ntp], gB + koff);
            }
#pragma unroll
            for (int mt = 0; mt < 4; mt++)
#pragma unroll
                for (int ntp = 0; ntp < 2; ntp++) {
                    mma16(accU[mt][ntp * 2 + 0], a[mt], &bu[ntp][0]);
                    mma16(accU[mt][ntp * 2 + 1], a[mt], &bu[ntp][2]);
                    mma16(accG[mt][ntp * 2 + 0], a[mt], &bg[ntp][0]);
                    mma16(accG[mt][ntp * 2 + 1], a[mt], &bg[ntp][2]);
                }
        }
        if (i + 2 < NIT) {
            int sn = (s + 2) % 3;
            loadStage(sn, (i + 2) * BK);
        }
        CP_COMMIT();
        s = (s + 1) % 3;
    }

    // epilogue: silu(up)*gate -> g_act (fp16)
#pragma unroll
    for (int mt = 0; mt < 4; mt++)
#pragma unroll
        for (int nt = 0; nt < 4; nt++) {
            int col = f0 + wn + nt * 8 + 2 * qc;
#pragma unroll
            for (int h = 0; h < 2; h++) {
                int r = row0 + wr + mt * 16 + qr + h * 8;
                if (r >= cnt) continue;
                float u0 = accU[mt][nt][h * 2 + 0], u1 = accU[mt][nt][h * 2 + 1];
                float g0 = accG[mt][nt][h * 2 + 0], g1 = accG[mt][nt][h * 2 + 1];
                float s0 = u0 / (1.0f + expf(-u0)) * g0;
                float s1 = u1 / (1.0f + expf(-u1)) * g1;
                *(__half2*)(g_act + ((size_t)e * T + r) * F + col) = __floats2half2_rn(s0, s1);
            }
        }
}

// ---------------- kernel 3: fp16 down GEMM + weighted scatter ----------------
// 128 threads, 4 warps (2x2), block tile 128x128, warp tile 64x64.
// BK=32, 3-stage pipeline, 3 CTAs/SM.
__global__ __launch_bounds__(128, 3) void down_kernel(float* __restrict__ y) {
    extern __shared__ uint32_t sm[];

    int e = blockIdx.x / MT;
    int mtile = blockIdx.x % MT;
    int cnt = g_count[e];
    int row0 = mtile * BM;
    if (row0 >= cnt) return;
    int n0 = blockIdx.y * 128;

    const __half* A = g_act + ((size_t)e * T + row0) * F;
    const __half* W = g_wd_h + (size_t)e * F * H + n0;

    int tid = threadIdx.x;
    uint32_t base = smem_u32(sm);

    auto loadStage = [&](int s, int kn) {
        uint32_t ad = base + (s * DWN_STAGE) * 4;
        uint32_t bd = ad + A_WORDS * 4;
        // A: 512 chunks -> 4/thread
#pragma unroll
        for (int j = 0; j < 4; j++) {
            int c = tid + j * 128;
            int m = c >> 2, seg = c & 3;
            cp16(ad + (m * ASTR + seg * 4) * 4,
                 A + (size_t)m * F + kn + seg * 8);
        }
        // B: 32 k-rows x 16 chunks = 512 -> 4/thread
#pragma unroll
        for (int j = 0; j < 4; j++) {
            int c = tid + j * 128;
            int kk = c >> 4, seg = c & 15;
            cp16(bd + (kk * BDSTR + seg * 4) * 4,
                 W + (size_t)(kn + kk) * H + seg * 8);
        }
    };

    loadStage(0, 0); CP_COMMIT();
    loadStage(1, BK); CP_COMMIT();

    int wid = tid >> 5, lane = tid & 31;
    int wr = (wid >> 1) * 64;
    int wn = (wid & 1) * 64;
    int qr = lane >> 2, qc = lane & 3;

    int lRow = lane & 15;
    int lHi  = (lane & 16) ? 4 : 0;
    uint32_t aLane = ((wr + lRow) * ASTR + lHi) * 4;
    uint32_t bLane = (lRow * BDSTR + (wn >> 1) + lHi) * 4;

    float acc[4][8][4];
#pragma unroll
    for (int mt = 0; mt < 4; mt++)
#pragma unroll
        for (int nt = 0; nt < 8; nt++)
#pragma unroll
            for (int i = 0; i < 4; i++) acc[mt][nt][i] = 0.0f;

    const int NIT = F / BK;   // 112
    int s = 0;
    for (int i = 0; i < NIT; i++) {
        CP_WAIT1();
        __syncthreads();

        uint32_t aB = base + (s * DWN_STAGE) * 4 + aLane;
        uint32_t bB = base + (s * DWN_STAGE + A_WORDS) * 4 + bLane;
#pragma unroll
        for (int ks = 0; ks < 2; ks++) {
            uint32_t a[4][4];
#pragma unroll
            for (int mt = 0; mt < 4; mt++)
                ldm_x4(a[mt], aB + (mt * 16 * ASTR + ks * 8) * 4);
            uint32_t bfr[4][4];
#pragma unroll
            for (int ntp = 0; ntp < 4; ntp++)
                ldm_x4t(bfr[ntp], bB + (ks * 16 * BDSTR + ntp * 8) * 4);
#pragma unroll
            for (int mt = 0; mt < 4; mt++)
#pragma unroll
                for (int ntp = 0; ntp < 4; ntp++) {
                    mma16(acc[mt][ntp * 2 + 0], a[mt], &bfr[ntp][0]);
                    mma16(acc[mt][ntp * 2 + 1], a[mt], &bfr[ntp][2]);
                }
        }
        if (i + 2 < NIT) {
            int sn = (s + 2) % 3;
            loadStage(sn, (i + 2) * BK);
        }
        CP_COMMIT();
        s = (s + 1) % 3;
    }

    // weighted scatter
#pragma unroll
    for (int mt = 0; mt < 4; mt++)
#pragma unroll
        for (int nt = 0; nt < 8; nt++) {
            int col = n0 + wn + nt * 8 + 2 * qc;
#pragma unroll
            for (int h = 0; h < 2; h++) {
                int r = row0 + wr + mt * 16 + qr + h * 8;
                if (r >= cnt) continue;
                int tok = g_idx[e * T + r];
                float wgt = g_wt[e * T + r];
                float* yr = y + (size_t)tok * H + col;
                atomicAdd(&yr[0], acc[mt][nt][h * 2 + 0] * wgt);
                atomicAdd(&yr[1], acc[mt][nt][h * 2 + 1] * wgt);
            }
        }
}

// ---------------- launch ----------------
extern "C" void kernel_launch(void* const* d_in, const int* in_sizes, int n_in,
                              void* d_out, int out_size) {
    const float* x     = (const float*)d_in[0];
    const float* gw    = (const float*)d_in[1];
    const float* wup   = (const float*)d_in[2];
    const float* wgate = (const float*)d_in[3];
    const float* wdown = (const float*)d_in[4];
    float* y = (float*)d_out;

    int write_logits = (out_size >= T * H + T * NE) ? 1 : 0;
    float* logits = y + (size_t)T * H;

    __half *wu_h, *wg_h, *wd_h;
    cudaGetSymbolAddress((void**)&wu_h, g_wu_h);
    cudaGetSymbolAddress((void**)&wg_h, g_wg_h);
    cudaGetSymbolAddress((void**)&wd_h, g_wd_h);

    cudaFuncSetAttribute(upgate_kernel, cudaFuncAttributeMaxDynamicSharedMemorySize, SMEM_UPG);
    cudaFuncSetAttribute(down_kernel,   cudaFuncAttributeMaxDynamicSharedMemorySize, SMEM_DWN);

    zero_kernel<<<256, 256>>>(y);
    int nw = NE * H * F / 4;
    cvth_kernel<<<2048, 256>>>((const float4*)wup,   (uint2*)wu_h, nw);
    cvth_kernel<<<2048, 256>>>((const float4*)wgate, (uint2*)wg_h, nw);
    cvth_kernel<<<2048, 256>>>((const float4*)wdown, (uint2*)wd_h, nw);
    router_kernel<<<T / 4, 128>>>(x, gw, logits, write_logits);
    upgate_kernel<<<dim3(NE * MT, F / 64), 128, SMEM_UPG>>>();
    down_kernel<<<dim3(NE * MT, H / 128), 128, SMEM_DWN>>>(y);
}